// round 5
// baseline (speedup 1.0000x reference)
#include <cuda_runtime.h>
#include <cuda_bf16.h>

typedef unsigned long long ull;

// Problem constants
#define BATCH 8
#define CHAN  256
#define HEADS 8
#define DHEAD 32
#define IH    32
#define IW    32
#define NTOK  1024
#define NPER  262144
#define WSZ   (9*256*256)
#define BIASN 3969

// ---------------- scratch ----------------
__device__ __align__(16) float g_wT[3][WSZ];            // [tap][ic][oc]
__device__ __align__(16) float g_woT[256*256];          // [c][o]
__device__ __align__(16) float g_act[3][BATCH*NPER];
__device__ __align__(16) float g_part[3][BATCH][32][2];
__device__ __align__(16) float g_attn[BATCH*NPER];

// ---------------- f32x2 helpers ----------------
__device__ __forceinline__ void ffma2(ull& d, ull a, ull b) {
    asm("fma.rn.f32x2 %0, %1, %2, %0;" : "+l"(d) : "l"(a), "l"(b));
}
__device__ __forceinline__ ull add2(ull a, ull b) {
    ull r; asm("add.rn.f32x2 %0, %1, %2;" : "=l"(r) : "l"(a), "l"(b)); return r;
}
__device__ __forceinline__ ull mul2(ull a, ull b) {
    ull r; asm("mul.rn.f32x2 %0, %1, %2;" : "=l"(r) : "l"(a), "l"(b)); return r;
}
__device__ __forceinline__ ull pack2(float a, float b) {
    ull u; asm("mov.b64 %0, {%1,%2};" : "=l"(u) : "f"(a), "f"(b)); return u;
}
__device__ __forceinline__ float lo2(ull u) { return __int_as_float((int)(unsigned)u); }
__device__ __forceinline__ float hi2(ull u) { return __int_as_float((int)(u >> 32)); }

// ---------------- 1) tiled weight transposes ----------------
__global__ void transpose_w_kernel(const float* __restrict__ wq,
                                   const float* __restrict__ wk,
                                   const float* __restrict__ wv,
                                   const float* __restrict__ wo) {
    const int p = blockIdx.z;
    const int F = (p < 3) ? 2304 : 256;
    if ((int)blockIdx.x * 32 >= F) return;
    const float* src = (p == 0) ? wq : (p == 1) ? wk : (p == 2) ? wv : wo;

    __shared__ float tile[32][33];
    const int f0 = blockIdx.x * 32;
    const int o0 = blockIdx.y * 32;

#pragma unroll
    for (int i = 0; i < 4; i++) {
        int oc = o0 + threadIdx.y + i * 8;
        tile[threadIdx.y + i * 8][threadIdx.x] = src[oc * F + f0 + threadIdx.x];
    }
    __syncthreads();

#pragma unroll
    for (int i = 0; i < 4; i++) {
        int f  = f0 + threadIdx.y + i * 8;
        int oc = o0 + threadIdx.x;
        float v = tile[threadIdx.x][threadIdx.y + i * 8];
        if (p < 3) {
            int ic  = f / 9;
            int tap = f - ic * 9;
            g_wT[p][tap * 65536 + ic * 256 + oc] = v;
        } else {
            g_woT[f * 256 + oc] = v;
        }
    }
}

// ---------------- 2) 3x3 conv, f32x2, 256 thr (oc-pair x half-row) ----------------
// grid: (32 rows, 8 batch, 3 proj), block 256
// thread: ocp = tid&127 -> oc (2*ocp, 2*ocp+1); half = tid>>7 -> px [16*half, 16*half+16)
__global__ void __launch_bounds__(256) conv3x3_kernel(const float* __restrict__ x) {
    const int hrow = blockIdx.x;
    const int b    = blockIdx.y;
    const int p    = blockIdx.z;
    const int tid  = threadIdx.x;
    const int ocp  = tid & 127;
    const int half = tid >> 7;

    __shared__ __align__(16) float2 s_in2[32][3][34];   // dup-packed input, 26KB
    __shared__ float  s_r1[256];
    __shared__ float  s_r2[256];

    ull acc[16];
#pragma unroll
    for (int px = 0; px < 16; px++) acc[px] = 0ull;

    const ull* wp = reinterpret_cast<const ull*>(g_wT[p]);

    for (int c0 = 0; c0 < 256; c0 += 32) {
        // cooperative load: 32 ic x 3 rows x 34 cols, duplicated
        for (int e = tid; e < 32 * 3 * 34; e += 256) {
            int ic = e / 102;
            int r  = e - ic * 102;
            int ky = r / 34;
            int wc = r - ky * 34;
            int wi = wc - 1;
            int hi = hrow + ky - 1;
            float v = 0.f;
            if ((unsigned)wi < 32u && (unsigned)hi < 32u)
                v = x[((b * 256 + c0 + ic) * 32 + hi) * 32 + wi];
            s_in2[ic][ky][wc] = make_float2(v, v);
        }
        __syncthreads();

        // prime weight double-buffer
        ull wcur[9];
#pragma unroll
        for (int tap = 0; tap < 9; tap++)
            wcur[tap] = wp[(tap * 256 + c0) * 128 + ocp];

        for (int ic = 0; ic < 32; ic++) {
            ull wnxt[9];
            const int icn = (ic + 1 < 32) ? (c0 + ic + 1) : (c0 + ic);
#pragma unroll
            for (int tap = 0; tap < 9; tap++)
                wnxt[tap] = wp[(tap * 256 + icn) * 128 + ocp];

#pragma unroll
            for (int ky = 0; ky < 3; ky++) {
                const ulonglong2* row2 =
                    reinterpret_cast<const ulonglong2*>(&s_in2[ic][ky][0]) + half * 8;
                ull r[18];
#pragma unroll
                for (int i = 0; i < 9; i++) {
                    ulonglong2 v = row2[i];
                    r[2 * i] = v.x; r[2 * i + 1] = v.y;
                }
#pragma unroll
                for (int kx = 0; kx < 3; kx++)
#pragma unroll
                    for (int px = 0; px < 16; px++)
                        ffma2(acc[px], wcur[ky * 3 + kx], r[px + kx]);
            }
#pragma unroll
            for (int tap = 0; tap < 9; tap++) wcur[tap] = wnxt[tap];
        }
        __syncthreads();
    }

    // writeback: oc 2*ocp (lo) and 2*ocp+1 (hi), 16 px starting at 16*half
    float* out_lo = &g_act[p][((b * 256 + 2 * ocp) * 32 + hrow) * 32 + half * 16];
    float* out_hi = &g_act[p][((b * 256 + 2 * ocp + 1) * 32 + hrow) * 32 + half * 16];
    float s = 0.f, sq = 0.f;
#pragma unroll
    for (int px = 0; px < 16; px += 4) {
        float a0 = lo2(acc[px]),     b0 = hi2(acc[px]);
        float a1 = lo2(acc[px + 1]), b1 = hi2(acc[px + 1]);
        float a2 = lo2(acc[px + 2]), b2 = hi2(acc[px + 2]);
        float a3 = lo2(acc[px + 3]), b3 = hi2(acc[px + 3]);
        *reinterpret_cast<float4*>(out_lo + px) = make_float4(a0, a1, a2, a3);
        *reinterpret_cast<float4*>(out_hi + px) = make_float4(b0, b1, b2, b3);
        s  += a0 + a1 + a2 + a3 + b0 + b1 + b2 + b3;
        sq += a0*a0 + a1*a1 + a2*a2 + a3*a3 + b0*b0 + b1*b1 + b2*b2 + b3*b3;
    }

    s_r1[tid] = s; s_r2[tid] = sq;
    __syncthreads();
    for (int st = 128; st > 0; st >>= 1) {
        if (tid < st) { s_r1[tid] += s_r1[tid + st]; s_r2[tid] += s_r2[tid + st]; }
        __syncthreads();
    }
    if (tid == 0) {
        g_part[p][b][hrow][0] = s_r1[0];
        g_part[p][b][hrow][1] = s_r2[0];
    }
}

// ---------------- 3) GroupNorm(1) + exact GELU ----------------
__global__ void gn_gelu_kernel(const float* __restrict__ gq, const float* __restrict__ bq,
                               const float* __restrict__ gk, const float* __restrict__ bk,
                               const float* __restrict__ gv, const float* __restrict__ bv) {
    const int chunk = blockIdx.x;
    const int b     = blockIdx.y;
    const int p     = blockIdx.z;
    const float* gg = (p == 0) ? gq : (p == 1) ? gk : gv;
    const float* bb = (p == 0) ? bq : (p == 1) ? bk : bv;

    __shared__ float s_mu, s_rs;
    if (threadIdx.x < 32) {
        float s  = g_part[p][b][threadIdx.x][0];
        float sq = g_part[p][b][threadIdx.x][1];
#pragma unroll
        for (int o = 16; o > 0; o >>= 1) {
            s  += __shfl_down_sync(0xffffffffu, s,  o);
            sq += __shfl_down_sync(0xffffffffu, sq, o);
        }
        if (threadIdx.x == 0) {
            float mu  = s / (float)NPER;
            float var = sq / (float)NPER - mu * mu;
            s_mu = mu;
            s_rs = rsqrtf(var + 1e-6f);
        }
    }
    __syncthreads();
    const float mu = s_mu, rs = s_rs;

    float* base = &g_act[p][b * NPER + chunk * 32768];
    for (int i = threadIdx.x; i < 8192; i += 256) {
        float4 v = reinterpret_cast<float4*>(base)[i];
        int c = (chunk * 32768 + i * 4) >> 10;
        float gc = gg[c], bc = bb[c];
        float t0 = (v.x - mu) * rs * gc + bc;
        float t1 = (v.y - mu) * rs * gc + bc;
        float t2 = (v.z - mu) * rs * gc + bc;
        float t3 = (v.w - mu) * rs * gc + bc;
        v.x = 0.5f * t0 * (1.0f + erff(t0 * 0.70710678118654752f));
        v.y = 0.5f * t1 * (1.0f + erff(t1 * 0.70710678118654752f));
        v.z = 0.5f * t2 * (1.0f + erff(t2 * 0.70710678118654752f));
        v.w = 0.5f * t3 * (1.0f + erff(t3 * 0.70710678118654752f));
        reinterpret_cast<float4*>(base)[i] = v;
    }
}

// ---------------- 4) flash attention, f32x2, scalar-Q, MUFU exp ----------------
// grid: (8 q-tiles, 8 heads, 8 batch), block 128 (one query per thread)
__global__ void __launch_bounds__(128) attn_kernel(const float* __restrict__ bias_table) {
    const int q0  = blockIdx.x * 128;
    const int h   = blockIdx.y;
    const int b   = blockIdx.z;
    const int tid = threadIdx.x;

    __shared__ __align__(16) float s_bias[BIASN + 3];   // 15888 B
    __shared__ __align__(16) float s_k[32 * 64];        // 8192 B  [d][j]
    __shared__ __align__(16) ull   s_v2T[64 * 18];      // 9216 B  [j][d2] pad 18

    for (int i = tid; i < BIASN; i += 128)
        s_bias[i] = bias_table[i * HEADS + h];

    const float* aq = &g_act[0][(b * 256 + h * DHEAD) * NTOK];
    const float* ak = &g_act[1][(b * 256 + h * DHEAD) * NTOK];
    const float* av = &g_act[2][(b * 256 + h * DHEAD) * NTOK];

    const int qi = q0 + tid;
    float qv[DHEAD];                        // scalar query (packs made per-use)
#pragma unroll
    for (int d = 0; d < DHEAD; d++) qv[d] = aq[d * NTOK + qi];

    const int yi = qi >> 5, xi = qi & 31;

    float m = -1e30f, l = 0.f;
    ull o2[16];
#pragma unroll
    for (int d2 = 0; d2 < 16; d2++) o2[d2] = 0ull;

    for (int kt = 0; kt < 16; kt++) {
        const int k0 = kt * 64;
        __syncthreads();
        for (int e = tid; e < 1024; e += 128) {
            int d2 = e >> 6, j = e & 63;
            float v0 = av[(2 * d2) * NTOK + k0 + j];
            float v1 = av[(2 * d2 + 1) * NTOK + k0 + j];
            s_k[(2 * d2) * 64 + j]     = ak[(2 * d2) * NTOK + k0 + j];
            s_k[(2 * d2 + 1) * 64 + j] = ak[(2 * d2 + 1) * NTOK + k0 + j];
            s_v2T[j * 18 + d2] = pack2(v0, v1);
        }
        __syncthreads();

        for (int sub = 0; sub < 2; sub++) {
            const int j0 = sub * 32;
            ull s2[16];
#pragma unroll
            for (int pp = 0; pp < 16; pp++) {
                int kg = k0 + j0 + 2 * pp;
                int yj = kg >> 5, xj = kg & 31;
                int idx0 = (yi - yj + 31) * 63 + (xi - xj + 31);
                int kg1 = kg + 1;
                int yj1 = kg1 >> 5, xj1 = kg1 & 31;
                int idx1 = (yi - yj1 + 31) * 63 + (xi - xj1 + 31);
                s2[pp] = pack2(s_bias[idx0], s_bias[idx1]);
            }
            // QK dot, 16B K loads; q dup-packed per-d on the fly
#pragma unroll
            for (int d = 0; d < DHEAD; d++) {
                const ull q2d = pack2(qv[d], qv[d]);
                const ulonglong2* krow =
                    reinterpret_cast<const ulonglong2*>(&s_k[d * 64 + j0]);
#pragma unroll
                for (int pq = 0; pq < 8; pq++) {
                    ulonglong2 kk = krow[pq];
                    ffma2(s2[2 * pq],     q2d, kk.x);
                    ffma2(s2[2 * pq + 1], q2d, kk.y);
                }
            }
            // online softmax (MUFU exp)
            float mn = m;
#pragma unroll
            for (int pp = 0; pp < 16; pp++)
                mn = fmaxf(mn, fmaxf(lo2(s2[pp]), hi2(s2[pp])));
            const float scale = __expf(m - mn);
            m = mn;
            ull ls2 = 0ull;
#pragma unroll
            for (int pp = 0; pp < 16; pp++) {
                float ea = __expf(lo2(s2[pp]) - mn);
                float eb = __expf(hi2(s2[pp]) - mn);
                s2[pp] = pack2(ea, eb);
                ls2 = add2(ls2, s2[pp]);
            }
            l = l * scale + lo2(ls2) + hi2(ls2);
            const ull sc2 = pack2(scale, scale);
#pragma unroll
            for (int d2 = 0; d2 < 16; d2++) o2[d2] = mul2(o2[d2], sc2);
            // PV, 16B V loads (V transposed)
#pragma unroll
            for (int jj = 0; jj < 32; jj++) {
                float pj = (jj & 1) ? hi2(s2[jj >> 1]) : lo2(s2[jj >> 1]);
                ull pj2 = pack2(pj, pj);
                const ulonglong2* vrow =
                    reinterpret_cast<const ulonglong2*>(&s_v2T[(j0 + jj) * 18]);
#pragma unroll
                for (int q8 = 0; q8 < 8; q8++) {
                    ulonglong2 vv = vrow[q8];
                    ffma2(o2[2 * q8],     pj2, vv.x);
                    ffma2(o2[2 * q8 + 1], pj2, vv.y);
                }
            }
        }
    }

    const float inv = 1.f / l;
    float* ao = &g_attn[(b * 256 + h * DHEAD) * NTOK];
#pragma unroll
    for (int d2 = 0; d2 < 16; d2++) {
        ao[(2 * d2) * NTOK + qi]     = lo2(o2[d2]) * inv;
        ao[(2 * d2 + 1) * NTOK + qi] = hi2(o2[d2]) * inv;
    }
}

// ---------------- 5) 1x1 output projection, f32x2 + LDS.128 ----------------
__global__ void outproj_kernel(const float* __restrict__ bo, float* __restrict__ out) {
    const int nt = blockIdx.x;
    const int b  = blockIdx.y;
    const int oc = threadIdx.x;

    __shared__ __align__(16) float s_a[256 * 32];
    for (int e = oc; e < 8192; e += 256) {
        int c = e >> 5, px = e & 31;
        s_a[e] = g_attn[(b * 256 + c) * NTOK + nt * 32 + px];
    }
    __syncthreads();

    ull acc[16];
#pragma unroll
    for (int p = 0; p < 16; p++) acc[p] = 0ull;

    for (int c = 0; c < 256; c++) {
        float wv = g_woT[c * 256 + oc];
        ull w2 = pack2(wv, wv);
        const ulonglong2* arow2 = reinterpret_cast<const ulonglong2*>(&s_a[c * 32]);
#pragma unroll
        for (int p8 = 0; p8 < 8; p8++) {
            ulonglong2 vv = arow2[p8];
            ffma2(acc[2 * p8],     w2, vv.x);
            ffma2(acc[2 * p8 + 1], w2, vv.y);
        }
    }

    const float bb = bo[oc];
    float* op = out + (b * 256 + oc) * NTOK + nt * 32;
#pragma unroll
    for (int p = 0; p < 16; p += 2) {
        float4 v4 = make_float4(lo2(acc[p]) + bb,     hi2(acc[p]) + bb,
                                lo2(acc[p + 1]) + bb, hi2(acc[p + 1]) + bb);
        *reinterpret_cast<float4*>(op + 2 * p) = v4;
    }
}

// ---------------- launch ----------------
extern "C" void kernel_launch(void* const* d_in, const int* in_sizes, int n_in,
                              void* d_out, int out_size) {
    const float* x  = (const float*)d_in[0];
    const float* wq = (const float*)d_in[1];
    const float* wk = (const float*)d_in[2];
    const float* wv = (const float*)d_in[3];
    const float* gq = (const float*)d_in[4];
    const float* bq = (const float*)d_in[5];
    const float* gk = (const float*)d_in[6];
    const float* bk = (const float*)d_in[7];
    const float* gv = (const float*)d_in[8];
    const float* bv = (const float*)d_in[9];
    const float* bt = (const float*)d_in[10];
    const float* wo = (const float*)d_in[11];
    const float* bo = (const float*)d_in[12];
    float* out = (float*)d_out;

    transpose_w_kernel<<<dim3(72, 8, 4), dim3(32, 8)>>>(wq, wk, wv, wo);
    conv3x3_kernel<<<dim3(32, BATCH, 3), 256>>>(x);
    gn_gelu_kernel<<<dim3(8, BATCH, 3), 256>>>(gq, bq, gk, bk, gv, bv);
    attn_kernel<<<dim3(8, HEADS, BATCH), 128>>>(bt);
    outproj_kernel<<<dim3(32, BATCH), 256>>>(bo, out);
}

// round 6
// speedup vs baseline: 1.0610x; 1.0610x over previous
#include <cuda_runtime.h>
#include <cuda_bf16.h>

typedef unsigned long long ull;

// Problem constants
#define BATCH 8
#define CHAN  256
#define HEADS 8
#define DHEAD 32
#define IH    32
#define IW    32
#define NTOK  1024
#define NPER  262144
#define WSZ   (9*256*256)
#define BIASN 3969

// ---------------- scratch ----------------
__device__ __align__(16) float g_wT[3][WSZ];            // [tap][ic][oc]
__device__ __align__(16) float g_woT[256*256];          // [c][o]
__device__ __align__(16) float g_act[3][BATCH*NPER];
__device__ __align__(16) float g_part[3][BATCH][32][2];
__device__ __align__(16) float g_attn[BATCH*NPER];

// ---------------- f32x2 helpers ----------------
__device__ __forceinline__ void ffma2(ull& d, ull a, ull b) {
    asm("fma.rn.f32x2 %0, %1, %2, %0;" : "+l"(d) : "l"(a), "l"(b));
}
__device__ __forceinline__ ull add2(ull a, ull b) {
    ull r; asm("add.rn.f32x2 %0, %1, %2;" : "=l"(r) : "l"(a), "l"(b)); return r;
}
__device__ __forceinline__ ull mul2(ull a, ull b) {
    ull r; asm("mul.rn.f32x2 %0, %1, %2;" : "=l"(r) : "l"(a), "l"(b)); return r;
}
__device__ __forceinline__ ull pack2(float a, float b) {
    ull u; asm("mov.b64 %0, {%1,%2};" : "=l"(u) : "f"(a), "f"(b)); return u;
}
__device__ __forceinline__ float lo2(ull u) { return __int_as_float((int)(unsigned)u); }
__device__ __forceinline__ float hi2(ull u) { return __int_as_float((int)(u >> 32)); }

// ---------------- 1) tiled weight transposes ----------------
__global__ void transpose_w_kernel(const float* __restrict__ wq,
                                   const float* __restrict__ wk,
                                   const float* __restrict__ wv,
                                   const float* __restrict__ wo) {
    const int p = blockIdx.z;
    const int F = (p < 3) ? 2304 : 256;
    if ((int)blockIdx.x * 32 >= F) return;
    const float* src = (p == 0) ? wq : (p == 1) ? wk : (p == 2) ? wv : wo;

    __shared__ float tile[32][33];
    const int f0 = blockIdx.x * 32;
    const int o0 = blockIdx.y * 32;

#pragma unroll
    for (int i = 0; i < 4; i++) {
        int oc = o0 + threadIdx.y + i * 8;
        tile[threadIdx.y + i * 8][threadIdx.x] = src[oc * F + f0 + threadIdx.x];
    }
    __syncthreads();

#pragma unroll
    for (int i = 0; i < 4; i++) {
        int f  = f0 + threadIdx.y + i * 8;
        int oc = o0 + threadIdx.x;
        float v = tile[threadIdx.x][threadIdx.y + i * 8];
        if (p < 3) {
            int ic  = f / 9;
            int tap = f - ic * 9;
            g_wT[p][tap * 65536 + ic * 256 + oc] = v;
        } else {
            g_woT[f * 256 + oc] = v;
        }
    }
}

// ---------------- 2) 3x3 conv, f32x2, prefetched weights (R4 version) ----------------
// grid: (32 rows, 8 batch, 3 proj), block 128 (thread t -> oc 2t, 2t+1)
__global__ void __launch_bounds__(128) conv3x3_kernel(const float* __restrict__ x) {
    const int hrow = blockIdx.x;
    const int b    = blockIdx.y;
    const int p    = blockIdx.z;
    const int t    = threadIdx.x;

    __shared__ __align__(16) float2 s_in2[32][3][34];   // dup-packed input, 26KB
    __shared__ float  s_r1[128];
    __shared__ float  s_r2[128];

    ull acc[32];
#pragma unroll
    for (int px = 0; px < 32; px++) acc[px] = 0ull;

    const ull* wp = reinterpret_cast<const ull*>(g_wT[p]);

    for (int c0 = 0; c0 < 256; c0 += 32) {
        // cooperative load: 32 ic x 3 rows x 34 cols, duplicated
        for (int e = t; e < 32 * 3 * 34; e += 128) {
            int ic = e / 102;
            int r  = e - ic * 102;
            int ky = r / 34;
            int wc = r - ky * 34;
            int wi = wc - 1;
            int hi = hrow + ky - 1;
            float v = 0.f;
            if ((unsigned)wi < 32u && (unsigned)hi < 32u)
                v = x[((b * 256 + c0 + ic) * 32 + hi) * 32 + wi];
            s_in2[ic][ky][wc] = make_float2(v, v);
        }
        __syncthreads();

        // prime weight double-buffer
        ull wcur[9];
#pragma unroll
        for (int tap = 0; tap < 9; tap++)
            wcur[tap] = wp[(tap * 256 + c0) * 128 + t];

        for (int ic = 0; ic < 32; ic++) {
            ull wnxt[9];
            const int icn = (ic + 1 < 32) ? (c0 + ic + 1) : (c0 + ic);
#pragma unroll
            for (int tap = 0; tap < 9; tap++)
                wnxt[tap] = wp[(tap * 256 + icn) * 128 + t];

#pragma unroll
            for (int ky = 0; ky < 3; ky++) {
                const ulonglong2* row2 =
                    reinterpret_cast<const ulonglong2*>(&s_in2[ic][ky][0]);
                ull r[18];
#pragma unroll
                for (int i = 0; i < 9; i++) {
                    ulonglong2 v = row2[i];
                    r[2 * i] = v.x; r[2 * i + 1] = v.y;
                }
#pragma unroll
                for (int kx = 0; kx < 3; kx++)
#pragma unroll
                    for (int px = 0; px < 16; px++)
                        ffma2(acc[px], wcur[ky * 3 + kx], r[px + kx]);
#pragma unroll
                for (int i = 0; i < 9; i++) {
                    ulonglong2 v = row2[8 + i];
                    r[2 * i] = v.x; r[2 * i + 1] = v.y;
                }
#pragma unroll
                for (int kx = 0; kx < 3; kx++)
#pragma unroll
                    for (int px = 0; px < 16; px++)
                        ffma2(acc[16 + px], wcur[ky * 3 + kx], r[px + kx]);
            }
#pragma unroll
            for (int tap = 0; tap < 9; tap++) wcur[tap] = wnxt[tap];
        }
        __syncthreads();
    }

    // writeback
    float* out_lo = &g_act[p][((b * 256 + 2 * t) * 32 + hrow) * 32];
    float* out_hi = &g_act[p][((b * 256 + 2 * t + 1) * 32 + hrow) * 32];
    float s = 0.f, sq = 0.f;
#pragma unroll
    for (int px = 0; px < 32; px += 4) {
        float a0 = lo2(acc[px]),     b0 = hi2(acc[px]);
        float a1 = lo2(acc[px + 1]), b1 = hi2(acc[px + 1]);
        float a2 = lo2(acc[px + 2]), b2 = hi2(acc[px + 2]);
        float a3 = lo2(acc[px + 3]), b3 = hi2(acc[px + 3]);
        *reinterpret_cast<float4*>(out_lo + px) = make_float4(a0, a1, a2, a3);
        *reinterpret_cast<float4*>(out_hi + px) = make_float4(b0, b1, b2, b3);
        s  += a0 + a1 + a2 + a3 + b0 + b1 + b2 + b3;
        sq += a0*a0 + a1*a1 + a2*a2 + a3*a3 + b0*b0 + b1*b1 + b2*b2 + b3*b3;
    }

    s_r1[t] = s; s_r2[t] = sq;
    __syncthreads();
    for (int st = 64; st > 0; st >>= 1) {
        if (t < st) { s_r1[t] += s_r1[t + st]; s_r2[t] += s_r2[t + st]; }
        __syncthreads();
    }
    if (t == 0) {
        g_part[p][b][hrow][0] = s_r1[0];
        g_part[p][b][hrow][1] = s_r2[0];
    }
}

// ---------------- 3) GroupNorm(1) + exact GELU ----------------
__global__ void gn_gelu_kernel(const float* __restrict__ gq, const float* __restrict__ bq,
                               const float* __restrict__ gk, const float* __restrict__ bk,
                               const float* __restrict__ gv, const float* __restrict__ bv) {
    const int chunk = blockIdx.x;
    const int b     = blockIdx.y;
    const int p     = blockIdx.z;
    const float* gg = (p == 0) ? gq : (p == 1) ? gk : gv;
    const float* bb = (p == 0) ? bq : (p == 1) ? bk : bv;

    __shared__ float s_mu, s_rs;
    if (threadIdx.x < 32) {
        float s  = g_part[p][b][threadIdx.x][0];
        float sq = g_part[p][b][threadIdx.x][1];
#pragma unroll
        for (int o = 16; o > 0; o >>= 1) {
            s  += __shfl_down_sync(0xffffffffu, s,  o);
            sq += __shfl_down_sync(0xffffffffu, sq, o);
        }
        if (threadIdx.x == 0) {
            float mu  = s / (float)NPER;
            float var = sq / (float)NPER - mu * mu;
            s_mu = mu;
            s_rs = rsqrtf(var + 1e-6f);
        }
    }
    __syncthreads();
    const float mu = s_mu, rs = s_rs;

    float* base = &g_act[p][b * NPER + chunk * 32768];
    for (int i = threadIdx.x; i < 8192; i += 256) {
        float4 v = reinterpret_cast<float4*>(base)[i];
        int c = (chunk * 32768 + i * 4) >> 10;
        float gc = gg[c], bc = bb[c];
        float t0 = (v.x - mu) * rs * gc + bc;
        float t1 = (v.y - mu) * rs * gc + bc;
        float t2 = (v.z - mu) * rs * gc + bc;
        float t3 = (v.w - mu) * rs * gc + bc;
        v.x = 0.5f * t0 * (1.0f + erff(t0 * 0.70710678118654752f));
        v.y = 0.5f * t1 * (1.0f + erff(t1 * 0.70710678118654752f));
        v.z = 0.5f * t2 * (1.0f + erff(t2 * 0.70710678118654752f));
        v.w = 0.5f * t3 * (1.0f + erff(t3 * 0.70710678118654752f));
        reinterpret_cast<float4*>(base)[i] = v;
    }
}

// ---------------- 4) flash attention, f32x2, Q in smem (occupancy) ----------------
// grid: (8 q-tiles, 8 heads, 8 batch), block 128 (one query per thread)
__global__ void __launch_bounds__(128, 4) attn_kernel(const float* __restrict__ bias_table) {
    const int q0  = blockIdx.x * 128;
    const int h   = blockIdx.y;
    const int b   = blockIdx.z;
    const int tid = threadIdx.x;

    __shared__ __align__(16) float s_bias[BIASN + 3];   // 15888 B
    __shared__ __align__(16) float s_q[32 * 128];       // 16384 B [d][q]
    __shared__ __align__(16) float s_k[32 * 64];        // 8192 B  [d][j]
    __shared__ __align__(16) ull   s_v2T[64 * 18];      // 9216 B  [j][d2] pad 18

    for (int i = tid; i < BIASN; i += 128)
        s_bias[i] = bias_table[i * HEADS + h];

    const float* aq = &g_act[0][(b * 256 + h * DHEAD) * NTOK];
    const float* ak = &g_act[1][(b * 256 + h * DHEAD) * NTOK];
    const float* av = &g_act[2][(b * 256 + h * DHEAD) * NTOK];

    const int qi = q0 + tid;
    // Q tile into smem (coalesced: thread tid loads q column tid for all d)
#pragma unroll
    for (int d = 0; d < DHEAD; d++)
        s_q[d * 128 + tid] = aq[d * NTOK + qi];

    const int yi = qi >> 5, xi = qi & 31;

    float m = -1e30f, l = 0.f;
    ull o2[16];
#pragma unroll
    for (int d2 = 0; d2 < 16; d2++) o2[d2] = 0ull;

    for (int kt = 0; kt < 16; kt++) {
        const int k0 = kt * 64;
        __syncthreads();
        for (int e = tid; e < 1024; e += 128) {
            int d2 = e >> 6, j = e & 63;
            float v0 = av[(2 * d2) * NTOK + k0 + j];
            float v1 = av[(2 * d2 + 1) * NTOK + k0 + j];
            s_k[(2 * d2) * 64 + j]     = ak[(2 * d2) * NTOK + k0 + j];
            s_k[(2 * d2 + 1) * 64 + j] = ak[(2 * d2 + 1) * NTOK + k0 + j];
            s_v2T[j * 18 + d2] = pack2(v0, v1);
        }
        __syncthreads();

        for (int sub = 0; sub < 2; sub++) {
            const int j0 = sub * 32;
            ull s2[16];
#pragma unroll
            for (int pp = 0; pp < 16; pp++) {
                int kg = k0 + j0 + 2 * pp;
                int yj = kg >> 5, xj = kg & 31;
                int idx0 = (yi - yj + 31) * 63 + (xi - xj + 31);
                int kg1 = kg + 1;
                int yj1 = kg1 >> 5, xj1 = kg1 & 31;
                int idx1 = (yi - yj1 + 31) * 63 + (xi - xj1 + 31);
                s2[pp] = pack2(s_bias[idx0], s_bias[idx1]);
            }
            // QK dot: q from smem (conflict-free), K via 16B broadcast loads
#pragma unroll
            for (int d = 0; d < DHEAD; d++) {
                float qd = s_q[d * 128 + tid];
                const ull q2d = pack2(qd, qd);
                const ulonglong2* krow =
                    reinterpret_cast<const ulonglong2*>(&s_k[d * 64 + j0]);
#pragma unroll
                for (int pq = 0; pq < 8; pq++) {
                    ulonglong2 kk = krow[pq];
                    ffma2(s2[2 * pq],     q2d, kk.x);
                    ffma2(s2[2 * pq + 1], q2d, kk.y);
                }
            }
            // online softmax (MUFU exp)
            float mn = m;
#pragma unroll
            for (int pp = 0; pp < 16; pp++)
                mn = fmaxf(mn, fmaxf(lo2(s2[pp]), hi2(s2[pp])));
            const float scale = __expf(m - mn);
            m = mn;
            ull ls2 = 0ull;
#pragma unroll
            for (int pp = 0; pp < 16; pp++) {
                float ea = __expf(lo2(s2[pp]) - mn);
                float eb = __expf(hi2(s2[pp]) - mn);
                s2[pp] = pack2(ea, eb);
                ls2 = add2(ls2, s2[pp]);
            }
            l = l * scale + lo2(ls2) + hi2(ls2);
            const ull sc2 = pack2(scale, scale);
#pragma unroll
            for (int d2 = 0; d2 < 16; d2++) o2[d2] = mul2(o2[d2], sc2);
            // PV, 16B V loads (V transposed)
#pragma unroll
            for (int jj = 0; jj < 32; jj++) {
                float pj = (jj & 1) ? hi2(s2[jj >> 1]) : lo2(s2[jj >> 1]);
                ull pj2 = pack2(pj, pj);
                const ulonglong2* vrow =
                    reinterpret_cast<const ulonglong2*>(&s_v2T[(j0 + jj) * 18]);
#pragma unroll
                for (int q8 = 0; q8 < 8; q8++) {
                    ulonglong2 vv = vrow[q8];
                    ffma2(o2[2 * q8],     pj2, vv.x);
                    ffma2(o2[2 * q8 + 1], pj2, vv.y);
                }
            }
        }
    }

    const float inv = 1.f / l;
    float* ao = &g_attn[(b * 256 + h * DHEAD) * NTOK];
#pragma unroll
    for (int d2 = 0; d2 < 16; d2++) {
        ao[(2 * d2) * NTOK + qi]     = lo2(o2[d2]) * inv;
        ao[(2 * d2 + 1) * NTOK + qi] = hi2(o2[d2]) * inv;
    }
}

// ---------------- 5) 1x1 output projection, f32x2 + LDS.128 ----------------
__global__ void outproj_kernel(const float* __restrict__ bo, float* __restrict__ out) {
    const int nt = blockIdx.x;
    const int b  = blockIdx.y;
    const int oc = threadIdx.x;

    __shared__ __align__(16) float s_a[256 * 32];
    for (int e = oc; e < 8192; e += 256) {
        int c = e >> 5, px = e & 31;
        s_a[e] = g_attn[(b * 256 + c) * NTOK + nt * 32 + px];
    }
    __syncthreads();

    ull acc[16];
#pragma unroll
    for (int p = 0; p < 16; p++) acc[p] = 0ull;

    for (int c = 0; c < 256; c++) {
        float wv = g_woT[c * 256 + oc];
        ull w2 = pack2(wv, wv);
        const ulonglong2* arow2 = reinterpret_cast<const ulonglong2*>(&s_a[c * 32]);
#pragma unroll
        for (int p8 = 0; p8 < 8; p8++) {
            ulonglong2 vv = arow2[p8];
            ffma2(acc[2 * p8],     w2, vv.x);
            ffma2(acc[2 * p8 + 1], w2, vv.y);
        }
    }

    const float bb = bo[oc];
    float* op = out + (b * 256 + oc) * NTOK + nt * 32;
#pragma unroll
    for (int p = 0; p < 16; p += 2) {
        float4 v4 = make_float4(lo2(acc[p]) + bb,     hi2(acc[p]) + bb,
                                lo2(acc[p + 1]) + bb, hi2(acc[p + 1]) + bb);
        *reinterpret_cast<float4*>(op + 2 * p) = v4;
    }
}

// ---------------- launch ----------------
extern "C" void kernel_launch(void* const* d_in, const int* in_sizes, int n_in,
                              void* d_out, int out_size) {
    const float* x  = (const float*)d_in[0];
    const float* wq = (const float*)d_in[1];
    const float* wk = (const float*)d_in[2];
    const float* wv = (const float*)d_in[3];
    const float* gq = (const float*)d_in[4];
    const float* bq = (const float*)d_in[5];
    const float* gk = (const float*)d_in[6];
    const float* bk = (const float*)d_in[7];
    const float* gv = (const float*)d_in[8];
    const float* bv = (const float*)d_in[9];
    const float* bt = (const float*)d_in[10];
    const float* wo = (const float*)d_in[11];
    const float* bo = (const float*)d_in[12];
    float* out = (float*)d_out;

    transpose_w_kernel<<<dim3(72, 8, 4), dim3(32, 8)>>>(wq, wk, wv, wo);
    conv3x3_kernel<<<dim3(32, BATCH, 3), 128>>>(x);
    gn_gelu_kernel<<<dim3(8, BATCH, 3), 256>>>(gq, bq, gk, bk, gv, bv);
    attn_kernel<<<dim3(8, HEADS, BATCH), 128>>>(bt);
    outproj_kernel<<<dim3(32, BATCH), 256>>>(bo, out);
}

// round 9
// speedup vs baseline: 1.2296x; 1.1590x over previous
#include <cuda_runtime.h>
#include <cuda_bf16.h>
#include <cstdint>
#include <cstring>

typedef unsigned long long ull;

// Problem constants
#define BATCH 8
#define CHAN  256
#define HEADS 8
#define DHEAD 32
#define NTOK  1024
#define NPER  262144
#define BIASN 3969

// ---------------- scratch ----------------
// W fragments, PTX mma B-fragment order: [p][tap][split][kc(16)][ntile(32)][lane(32)][4 bf16]
__device__ __align__(16) __nv_bfloat16 g_wfragB[3*9*2*16*32*32*4];
// X transposed+padded bf16 split: [b][split][y(34)][x(34)][c(256)]
__device__ __align__(16) __nv_bfloat16 g_xbfT[8*2*34*34*256];
__device__ __align__(16) float g_woT[256*256];                 // [c][o]
__device__ __align__(16) float g_act[3][BATCH*NPER];           // conv->gelu activations
__device__ __align__(16) float g_part[3][BATCH][32][2];        // GN partials
__device__ __align__(16) float g_attn[BATCH*NPER];

// ---------------- f32x2 helpers ----------------
__device__ __forceinline__ void ffma2(ull& d, ull a, ull b) {
    asm("fma.rn.f32x2 %0, %1, %2, %0;" : "+l"(d) : "l"(a), "l"(b));
}
__device__ __forceinline__ ull add2(ull a, ull b) {
    ull r; asm("add.rn.f32x2 %0, %1, %2;" : "=l"(r) : "l"(a), "l"(b)); return r;
}
__device__ __forceinline__ ull mul2(ull a, ull b) {
    ull r; asm("mul.rn.f32x2 %0, %1, %2;" : "=l"(r) : "l"(a), "l"(b)); return r;
}
__device__ __forceinline__ ull pack2(float a, float b) {
    ull u; asm("mov.b64 %0, {%1,%2};" : "=l"(u) : "f"(a), "f"(b)); return u;
}
__device__ __forceinline__ float lo2(ull u) { return __int_as_float((int)(unsigned)u); }
__device__ __forceinline__ float hi2(ull u) { return __int_as_float((int)(u >> 32)); }

// ---------------- warp mma helper (bf16, fp32 accum) ----------------
__device__ __forceinline__ void mma16816(float* c, const uint32_t* a, const uint32_t* b) {
    asm volatile("mma.sync.aligned.m16n8k16.row.col.f32.bf16.bf16.f32 "
        "{%0,%1,%2,%3}, {%4,%5,%6,%7}, {%8,%9}, {%0,%1,%2,%3};"
        : "+f"(c[0]), "+f"(c[1]), "+f"(c[2]), "+f"(c[3])
        : "r"(a[0]), "r"(a[1]), "r"(a[2]), "r"(a[3]), "r"(b[0]), "r"(b[1]));
}

// ---------------- 1a) weight prep into B-fragment order, bf16 split ----------------
// grid (64, 9, 3), block 256. Fragment: lane holds W[oc=nt*8+g][ic = kc*16 + {2t,2t+1,2t+8,2t+9}]
__global__ void prep_w_kernel(const float* __restrict__ wq,
                              const float* __restrict__ wk,
                              const float* __restrict__ wv) {
    const int sub = threadIdx.x >> 5, lane = threadIdx.x & 31;
    const int fi = blockIdx.x * 8 + sub;         // 0..511 = (kc, ntile)
    const int kc = fi >> 5, ntile = fi & 31;
    const int tap = blockIdx.y, p = blockIdx.z;
    const float* w = (p == 0) ? wq : (p == 1) ? wk : wv;
    const int t = lane & 3, g = lane >> 2;
    const int oc = ntile * 8 + g;
    const int k0 = kc * 16 + t * 2;

    float v0 = w[oc * 2304 + (k0    ) * 9 + tap];
    float v1 = w[oc * 2304 + (k0 + 1) * 9 + tap];
    float v2 = w[oc * 2304 + (k0 + 8) * 9 + tap];
    float v3 = w[oc * 2304 + (k0 + 9) * 9 + tap];

    __nv_bfloat16 h0 = __float2bfloat16(v0), h1 = __float2bfloat16(v1);
    __nv_bfloat16 h2 = __float2bfloat16(v2), h3 = __float2bfloat16(v3);
    __nv_bfloat16 l0 = __float2bfloat16(v0 - __bfloat162float(h0));
    __nv_bfloat16 l1 = __float2bfloat16(v1 - __bfloat162float(h1));
    __nv_bfloat16 l2 = __float2bfloat16(v2 - __bfloat162float(h2));
    __nv_bfloat16 l3 = __float2bfloat16(v3 - __bfloat162float(h3));

    int base = ((((p * 9 + tap) * 2 + 0) * 16 + kc) * 32 + ntile) * 32 + lane;  // frag units
    __nv_bfloat16* dh = g_wfragB + base * 4;
    dh[0] = h0; dh[1] = h1; dh[2] = h2; dh[3] = h3;
    __nv_bfloat16* dl = dh + 16 * 32 * 32 * 4;   // split stride
    dl[0] = l0; dl[1] = l1; dl[2] = l2; dl[3] = l3;
}

// ---------------- 1b) input transpose + pad + bf16-split ----------------
// grid (34 y, 8 b), block 256 (c)
__global__ void prep_x_kernel(const float* __restrict__ x) {
    const int y = blockIdx.x, b = blockIdx.y, c = threadIdx.x;
    __shared__ float s_t[256][33];
    const bool rowvalid = (y >= 1 && y <= 32);
    if (rowvalid) {
        const float* src = x + ((b * 256 + c) * 32 + (y - 1)) * 32;
#pragma unroll
        for (int i = 0; i < 8; i++) {
            float4 v = reinterpret_cast<const float4*>(src)[i];
            s_t[c][i * 4 + 0] = v.x; s_t[c][i * 4 + 1] = v.y;
            s_t[c][i * 4 + 2] = v.z; s_t[c][i * 4 + 3] = v.w;
        }
    }
    __syncthreads();
    for (int xx = 0; xx < 34; xx++) {
        float v = (rowvalid && xx >= 1 && xx <= 32) ? s_t[c][xx - 1] : 0.f;
        __nv_bfloat16 hi = __float2bfloat16(v);
        __nv_bfloat16 lo = __float2bfloat16(v - __bfloat162float(hi));
        int base = (((b * 2) * 34 + y) * 34 + xx) * 256 + c;
        g_xbfT[base]              = hi;
        g_xbfT[base + 34*34*256]  = lo;
    }
}

// ---------------- 1c) wo transpose ----------------
__global__ void transpose_wo_kernel(const float* __restrict__ wo) {
    __shared__ float tile[32][33];
    const int c0 = blockIdx.x * 32, o0 = blockIdx.y * 32;
#pragma unroll
    for (int i = 0; i < 4; i++)
        tile[threadIdx.y + i * 8][threadIdx.x] = wo[(o0 + threadIdx.y + i * 8) * 256 + c0 + threadIdx.x];
    __syncthreads();
#pragma unroll
    for (int i = 0; i < 4; i++)
        g_woT[(c0 + threadIdx.y + i * 8) * 256 + o0 + threadIdx.x] =
            tile[threadIdx.x][threadIdx.y + i * 8];
}

// ---------------- 2) conv via mma.sync bf16-split-3, fused GN partials ----------------
// grid (16 pxtiles of 64, 6 = octile*3? decoded p=y>>1 och=y&1, 8 b), block 256 (8 warps)
// CTA tile: D[64 px][128 oc]; warp [32 px][32 oc]; D = X^T(A, row-major) * W^T(B, frag-prepped)
__global__ void __launch_bounds__(256) conv_mma_kernel() {
    const int nt  = blockIdx.x;
    const int p   = blockIdx.y >> 1, och = blockIdx.y & 1;
    const int b   = blockIdx.z;
    const int tid = threadIdx.x, warp = tid >> 5, lane = tid & 31;
    const int wm = warp & 1, wn = warp >> 1;
    const int g = lane >> 2, t = lane & 3;
    const int px_warp = nt * 64 + wm * 32;

    float acc[2][4][4];
#pragma unroll
    for (int mt = 0; mt < 2; mt++)
#pragma unroll
        for (int n8 = 0; n8 < 4; n8++)
#pragma unroll
            for (int r = 0; r < 4; r++) acc[mt][n8][r] = 0.f;

    for (int tap = 0; tap < 9; tap++) {
        const int ky = tap / 3, kx = tap - ky * 3;
        for (int kc = 0; kc < 16; kc++) {
            // A fragments (X^T), both splits
            uint32_t afr[2][2][4];
#pragma unroll
            for (int mt = 0; mt < 2; mt++) {
                const int px  = px_warp + mt * 16 + g;
                const int y   = (px >> 5) + ky;
                const int x   = (px & 31) + kx;
                const int ic0 = kc * 16 + t * 2;
#pragma unroll
                for (int sp = 0; sp < 2; sp++) {
                    const __nv_bfloat16* xp =
                        g_xbfT + (((b * 2 + sp) * 34 + y) * 34 + x) * 256 + ic0;
                    afr[sp][mt][0] = *reinterpret_cast<const uint32_t*>(xp);
                    afr[sp][mt][2] = *reinterpret_cast<const uint32_t*>(xp + 8);
                    afr[sp][mt][1] = *reinterpret_cast<const uint32_t*>(xp + 2048);      // px+8
                    afr[sp][mt][3] = *reinterpret_cast<const uint32_t*>(xp + 2048 + 8);
                }
            }
            // B fragments (W, prepped), both splits
            uint32_t bfr[2][4][2];
#pragma unroll
            for (int sp = 0; sp < 2; sp++) {
                const ull* wb = reinterpret_cast<const ull*>(g_wfragB)
                    + ((((p * 9 + tap) * 2 + sp) * 16 + kc) * 32) * 32 + lane;
#pragma unroll
                for (int n8 = 0; n8 < 4; n8++) {
                    ull v = wb[(och * 16 + wn * 4 + n8) * 32];
                    bfr[sp][n8][0] = (uint32_t)v;
                    bfr[sp][n8][1] = (uint32_t)(v >> 32);
                }
            }
            // 3 split combos: (w_hi,x_hi), (w_hi,x_lo), (w_lo,x_hi)
#pragma unroll
            for (int combo = 0; combo < 3; combo++) {
                const int ws = combo >> 1, xs = combo & 1;
#pragma unroll
                for (int mt = 0; mt < 2; mt++)
#pragma unroll
                    for (int n8 = 0; n8 < 4; n8++)
                        mma16816(acc[mt][n8], afr[xs][mt], bfr[ws][n8]);
            }
        }
    }

    // epilogue: scatter D to g_act [oc][px], GN partial sums
    float s = 0.f, sq = 0.f;
#pragma unroll
    for (int mt = 0; mt < 2; mt++)
#pragma unroll
        for (int n8 = 0; n8 < 4; n8++)
#pragma unroll
            for (int r = 0; r < 4; r++) {
                float v  = acc[mt][n8][r];
                int   px = px_warp + mt * 16 + g + ((r >> 1) << 3);
                int   oc = och * 128 + wn * 32 + n8 * 8 + t * 2 + (r & 1);
                g_act[p][(b * 256 + oc) * 1024 + px] = v;
                s += v; sq += v * v;
            }
    __shared__ float red[512];
    red[tid] = s; red[tid + 256] = sq;
    __syncthreads();
    for (int st = 128; st > 0; st >>= 1) {
        if (tid < st) { red[tid] += red[tid + st]; red[tid + 256] += red[tid + 256 + st]; }
        __syncthreads();
    }
    if (tid == 0) {
        g_part[p][b][nt * 2 + och][0] = red[0];
        g_part[p][b][nt * 2 + och][1] = red[256];
    }
}

// ---------------- 3) GroupNorm(1) + exact GELU ----------------
__global__ void gn_gelu_kernel(const float* __restrict__ gq, const float* __restrict__ bq,
                               const float* __restrict__ gk, const float* __restrict__ bk,
                               const float* __restrict__ gv, const float* __restrict__ bv) {
    const int chunk = blockIdx.x;
    const int b     = blockIdx.y;
    const int p     = blockIdx.z;
    const float* gg = (p == 0) ? gq : (p == 1) ? gk : gv;
    const float* bb = (p == 0) ? bq : (p == 1) ? bk : bv;

    __shared__ float s_mu, s_rs;
    if (threadIdx.x < 32) {
        float s  = g_part[p][b][threadIdx.x][0];
        float sq = g_part[p][b][threadIdx.x][1];
#pragma unroll
        for (int o = 16; o > 0; o >>= 1) {
            s  += __shfl_down_sync(0xffffffffu, s,  o);
            sq += __shfl_down_sync(0xffffffffu, sq, o);
        }
        if (threadIdx.x == 0) {
            float mu  = s / (float)NPER;
            float var = sq / (float)NPER - mu * mu;
            s_mu = mu;
            s_rs = rsqrtf(var + 1e-6f);
        }
    }
    __syncthreads();
    const float mu = s_mu, rs = s_rs;

    float* base = &g_act[p][b * NPER + chunk * 32768];
    for (int i = threadIdx.x; i < 8192; i += 256) {
        float4 v = reinterpret_cast<float4*>(base)[i];
        int c = (chunk * 32768 + i * 4) >> 10;
        float gc = gg[c], bc = bb[c];
        float t0 = (v.x - mu) * rs * gc + bc;
        float t1 = (v.y - mu) * rs * gc + bc;
        float t2 = (v.z - mu) * rs * gc + bc;
        float t3 = (v.w - mu) * rs * gc + bc;
        v.x = 0.5f * t0 * (1.0f + erff(t0 * 0.70710678118654752f));
        v.y = 0.5f * t1 * (1.0f + erff(t1 * 0.70710678118654752f));
        v.z = 0.5f * t2 * (1.0f + erff(t2 * 0.70710678118654752f));
        v.w = 0.5f * t3 * (1.0f + erff(t3 * 0.70710678118654752f));
        reinterpret_cast<float4*>(base)[i] = v;
    }
}

// ---------------- 4) flash attention (R6 version) ----------------
__global__ void __launch_bounds__(128, 4) attn_kernel(const float* __restrict__ bias_table) {
    const int q0  = blockIdx.x * 128;
    const int h   = blockIdx.y;
    const int b   = blockIdx.z;
    const int tid = threadIdx.x;

    __shared__ __align__(16) float s_bias[BIASN + 3];
    __shared__ __align__(16) float s_q[32 * 128];
    __shared__ __align__(16) float s_k[32 * 64];
    __shared__ __align__(16) ull   s_v2T[64 * 18];

    for (int i = tid; i < BIASN; i += 128)
        s_bias[i] = bias_table[i * HEADS + h];

    const float* aq = &g_act[0][(b * 256 + h * DHEAD) * NTOK];
    const float* ak = &g_act[1][(b * 256 + h * DHEAD) * NTOK];
    const float* av = &g_act[2][(b * 256 + h * DHEAD) * NTOK];

    const int qi = q0 + tid;
#pragma unroll
    for (int d = 0; d < DHEAD; d++)
        s_q[d * 128 + tid] = aq[d * NTOK + qi];

    const int yi = qi >> 5, xi = qi & 31;

    float m = -1e30f, l = 0.f;
    ull o2[16];
#pragma unroll
    for (int d2 = 0; d2 < 16; d2++) o2[d2] = 0ull;

    for (int kt = 0; kt < 16; kt++) {
        const int k0 = kt * 64;
        __syncthreads();
        for (int e = tid; e < 1024; e += 128) {
            int d2 = e >> 6, j = e & 63;
            float v0 = av[(2 * d2) * NTOK + k0 + j];
            float v1 = av[(2 * d2 + 1) * NTOK + k0 + j];
            s_k[(2 * d2) * 64 + j]     = ak[(2 * d2) * NTOK + k0 + j];
            s_k[(2 * d2 + 1) * 64 + j] = ak[(2 * d2 + 1) * NTOK + k0 + j];
            s_v2T[j * 18 + d2] = pack2(v0, v1);
        }
        __syncthreads();

        for (int sub = 0; sub < 2; sub++) {
            const int j0 = sub * 32;
            ull s2[16];
#pragma unroll
            for (int pp = 0; pp < 16; pp++) {
                int kg = k0 + j0 + 2 * pp;
                int yj = kg >> 5, xj = kg & 31;
                int idx0 = (yi - yj + 31) * 63 + (xi - xj + 31);
                int kg1 = kg + 1;
                int yj1 = kg1 >> 5, xj1 = kg1 & 31;
                int idx1 = (yi - yj1 + 31) * 63 + (xi - xj1 + 31);
                s2[pp] = pack2(s_bias[idx0], s_bias[idx1]);
            }
#pragma unroll
            for (int d = 0; d < DHEAD; d++) {
                float qd = s_q[d * 128 + tid];
                const ull q2d = pack2(qd, qd);
                const ulonglong2* krow =
                    reinterpret_cast<const ulonglong2*>(&s_k[d * 64 + j0]);
#pragma unroll
                for (int pq = 0; pq < 8; pq++) {
                    ulonglong2 kk = krow[pq];
                    ffma2(s2[2 * pq],     q2d, kk.x);
                    ffma2(s2[2 * pq + 1], q2d, kk.y);
                }
            }
            float mn = m;
#pragma unroll
            for (int pp = 0; pp < 16; pp++)
                mn = fmaxf(mn, fmaxf(lo2(s2[pp]), hi2(s2[pp])));
            const float scale = __expf(m - mn);
            m = mn;
            ull ls2 = 0ull;
#pragma unroll
            for (int pp = 0; pp < 16; pp++) {
                float ea = __expf(lo2(s2[pp]) - mn);
                float eb = __expf(hi2(s2[pp]) - mn);
                s2[pp] = pack2(ea, eb);
                ls2 = add2(ls2, s2[pp]);
            }
            l = l * scale + lo2(ls2) + hi2(ls2);
            const ull sc2 = pack2(scale, scale);
#pragma unroll
            for (int d2 = 0; d2 < 16; d2++) o2[d2] = mul2(o2[d2], sc2);
#pragma unroll
            for (int jj = 0; jj < 32; jj++) {
                float pj = (jj & 1) ? hi2(s2[jj >> 1]) : lo2(s2[jj >> 1]);
                ull pj2 = pack2(pj, pj);
                const ulonglong2* vrow =
                    reinterpret_cast<const ulonglong2*>(&s_v2T[(j0 + jj) * 18]);
#pragma unroll
                for (int q8 = 0; q8 < 8; q8++) {
                    ulonglong2 vv = vrow[q8];
                    ffma2(o2[2 * q8],     pj2, vv.x);
                    ffma2(o2[2 * q8 + 1], pj2, vv.y);
                }
            }
        }
    }

    const float inv = 1.f / l;
    float* ao = &g_attn[(b * 256 + h * DHEAD) * NTOK];
#pragma unroll
    for (int d2 = 0; d2 < 16; d2++) {
        ao[(2 * d2) * NTOK + qi]     = lo2(o2[d2]) * inv;
        ao[(2 * d2 + 1) * NTOK + qi] = hi2(o2[d2]) * inv;
    }
}

// ---------------- 5) 1x1 output projection ----------------
__global__ void outproj_kernel(const float* __restrict__ bo, float* __restrict__ out) {
    const int nt = blockIdx.x;
    const int b  = blockIdx.y;
    const int oc = threadIdx.x;

    __shared__ __align__(16) float s_a[256 * 32];
    for (int e = oc; e < 8192; e += 256) {
        int c = e >> 5, px = e & 31;
        s_a[e] = g_attn[(b * 256 + c) * NTOK + nt * 32 + px];
    }
    __syncthreads();

    ull acc[16];
#pragma unroll
    for (int p = 0; p < 16; p++) acc[p] = 0ull;

    for (int c = 0; c < 256; c++) {
        float wv = g_woT[c * 256 + oc];
        ull w2 = pack2(wv, wv);
        const ulonglong2* arow2 = reinterpret_cast<const ulonglong2*>(&s_a[c * 32]);
#pragma unroll
        for (int p8 = 0; p8 < 8; p8++) {
            ulonglong2 vv = arow2[p8];
            ffma2(acc[2 * p8],     w2, vv.x);
            ffma2(acc[2 * p8 + 1], w2, vv.y);
        }
    }

    const float bb = bo[oc];
    float* op = out + (b * 256 + oc) * NTOK + nt * 32;
#pragma unroll
    for (int p = 0; p < 16; p += 2) {
        float4 v4 = make_float4(lo2(acc[p]) + bb,     hi2(acc[p]) + bb,
                                lo2(acc[p + 1]) + bb, hi2(acc[p + 1]) + bb);
        *reinterpret_cast<float4*>(op + 2 * p) = v4;
    }
}

// ---------------- launch ----------------
extern "C" void kernel_launch(void* const* d_in, const int* in_sizes, int n_in,
                              void* d_out, int out_size) {
    const float* x  = (const float*)d_in[0];
    const float* wq = (const float*)d_in[1];
    const float* wk = (const float*)d_in[2];
    const float* wv = (const float*)d_in[3];
    const float* gq = (const float*)d_in[4];
    const float* bq = (const float*)d_in[5];
    const float* gk = (const float*)d_in[6];
    const float* bk = (const float*)d_in[7];
    const float* gv = (const float*)d_in[8];
    const float* bv = (const float*)d_in[9];
    const float* bt = (const float*)d_in[10];
    const float* wo = (const float*)d_in[11];
    const float* bo = (const float*)d_in[12];
    float* out = (float*)d_out;

    prep_w_kernel<<<dim3(64, 9, 3), 256>>>(wq, wk, wv);
    prep_x_kernel<<<dim3(34, BATCH), 256>>>(x);
    transpose_wo_kernel<<<dim3(8, 8), dim3(32, 8)>>>(wo);
    conv_mma_kernel<<<dim3(16, 6, BATCH), 256>>>();
    gn_gelu_kernel<<<dim3(8, BATCH, 3), 256>>>(gq, bq, gk, bk, gv, bv);
    attn_kernel<<<dim3(8, HEADS, BATCH), 128>>>(bt);
    outproj_kernel<<<dim3(32, BATCH), 256>>>(bo, out);
}

// round 10
// speedup vs baseline: 1.6080x; 1.3077x over previous
#include <cuda_runtime.h>
#include <cuda_bf16.h>
#include <cstdint>
#include <cstring>

typedef unsigned long long ull;

// Problem constants
#define BATCH 8
#define CHAN  256
#define HEADS 8
#define DHEAD 32
#define NTOK  1024
#define NPER  262144
#define BIASN 3969

// ---------------- scratch ----------------
// W fragments, PTX mma B-fragment order: [p][tap][split][kc(16)][ntile(32)][lane(32)][4 bf16]
__device__ __align__(16) __nv_bfloat16 g_wfragB[3*9*2*16*32*32*4];
// X transposed+padded bf16 split: [b][split][y(34)][x(34)][c(256)]
__device__ __align__(16) __nv_bfloat16 g_xbfT[8*2*34*34*256];
__device__ __align__(16) float g_woT[256*256];                 // [c][o]
__device__ __align__(16) float g_act[3][BATCH*NPER];           // conv->gelu activations
__device__ __align__(16) float g_part[3][BATCH][16][2];        // GN partials (16 ntiles)
__device__ __align__(16) float g_attn[BATCH*NPER];

// ---------------- f32x2 helpers ----------------
__device__ __forceinline__ void ffma2(ull& d, ull a, ull b) {
    asm("fma.rn.f32x2 %0, %1, %2, %0;" : "+l"(d) : "l"(a), "l"(b));
}
__device__ __forceinline__ ull add2(ull a, ull b) {
    ull r; asm("add.rn.f32x2 %0, %1, %2;" : "=l"(r) : "l"(a), "l"(b)); return r;
}
__device__ __forceinline__ ull mul2(ull a, ull b) {
    ull r; asm("mul.rn.f32x2 %0, %1, %2;" : "=l"(r) : "l"(a), "l"(b)); return r;
}
__device__ __forceinline__ ull pack2(float a, float b) {
    ull u; asm("mov.b64 %0, {%1,%2};" : "=l"(u) : "f"(a), "f"(b)); return u;
}
__device__ __forceinline__ float lo2(ull u) { return __int_as_float((int)(unsigned)u); }
__device__ __forceinline__ float hi2(ull u) { return __int_as_float((int)(u >> 32)); }

// ---------------- warp mma helper (bf16, fp32 accum) ----------------
__device__ __forceinline__ void mma16816(float* c, const uint32_t* a, const uint32_t* b) {
    asm volatile("mma.sync.aligned.m16n8k16.row.col.f32.bf16.bf16.f32 "
        "{%0,%1,%2,%3}, {%4,%5,%6,%7}, {%8,%9}, {%0,%1,%2,%3};"
        : "+f"(c[0]), "+f"(c[1]), "+f"(c[2]), "+f"(c[3])
        : "r"(a[0]), "r"(a[1]), "r"(a[2]), "r"(a[3]), "r"(b[0]), "r"(b[1]));
}

// ---------------- 1a) weight prep into B-fragment order, bf16 split ----------------
// grid (64, 9, 3), block 256. Lane holds W[oc=ntile*8+g][ic = kc*16 + {2t,2t+1,2t+8,2t+9}]
__global__ void prep_w_kernel(const float* __restrict__ wq,
                              const float* __restrict__ wk,
                              const float* __restrict__ wv) {
    const int sub = threadIdx.x >> 5, lane = threadIdx.x & 31;
    const int fi = blockIdx.x * 8 + sub;         // 0..511 = (kc, ntile)
    const int kc = fi >> 5, ntile = fi & 31;
    const int tap = blockIdx.y, p = blockIdx.z;
    const float* w = (p == 0) ? wq : (p == 1) ? wk : wv;
    const int t = lane & 3, g = lane >> 2;
    const int oc = ntile * 8 + g;
    const int k0 = kc * 16 + t * 2;

    float v0 = w[oc * 2304 + (k0    ) * 9 + tap];
    float v1 = w[oc * 2304 + (k0 + 1) * 9 + tap];
    float v2 = w[oc * 2304 + (k0 + 8) * 9 + tap];
    float v3 = w[oc * 2304 + (k0 + 9) * 9 + tap];

    __nv_bfloat16 h0 = __float2bfloat16(v0), h1 = __float2bfloat16(v1);
    __nv_bfloat16 h2 = __float2bfloat16(v2), h3 = __float2bfloat16(v3);
    __nv_bfloat16 l0 = __float2bfloat16(v0 - __bfloat162float(h0));
    __nv_bfloat16 l1 = __float2bfloat16(v1 - __bfloat162float(h1));
    __nv_bfloat16 l2 = __float2bfloat16(v2 - __bfloat162float(h2));
    __nv_bfloat16 l3 = __float2bfloat16(v3 - __bfloat162float(h3));

    int base = ((((p * 9 + tap) * 2 + 0) * 16 + kc) * 32 + ntile) * 32 + lane;
    __nv_bfloat16* dh = g_wfragB + base * 4;
    dh[0] = h0; dh[1] = h1; dh[2] = h2; dh[3] = h3;
    __nv_bfloat16* dl = dh + 16 * 32 * 32 * 4;
    dl[0] = l0; dl[1] = l1; dl[2] = l2; dl[3] = l3;
}

// ---------------- 1b) input transpose + pad + bf16-split ----------------
__global__ void prep_x_kernel(const float* __restrict__ x) {
    const int y = blockIdx.x, b = blockIdx.y, c = threadIdx.x;
    __shared__ float s_t[256][33];
    const bool rowvalid = (y >= 1 && y <= 32);
    if (rowvalid) {
        const float* src = x + ((b * 256 + c) * 32 + (y - 1)) * 32;
#pragma unroll
        for (int i = 0; i < 8; i++) {
            float4 v = reinterpret_cast<const float4*>(src)[i];
            s_t[c][i * 4 + 0] = v.x; s_t[c][i * 4 + 1] = v.y;
            s_t[c][i * 4 + 2] = v.z; s_t[c][i * 4 + 3] = v.w;
        }
    }
    __syncthreads();
    for (int xx = 0; xx < 34; xx++) {
        float v = (rowvalid && xx >= 1 && xx <= 32) ? s_t[c][xx - 1] : 0.f;
        __nv_bfloat16 hi = __float2bfloat16(v);
        __nv_bfloat16 lo = __float2bfloat16(v - __bfloat162float(hi));
        int base = (((b * 2) * 34 + y) * 34 + xx) * 256 + c;
        g_xbfT[base]              = hi;
        g_xbfT[base + 34*34*256]  = lo;
    }
}

// ---------------- 1c) wo transpose ----------------
__global__ void transpose_wo_kernel(const float* __restrict__ wo) {
    __shared__ float tile[32][33];
    const int c0 = blockIdx.x * 32, o0 = blockIdx.y * 32;
#pragma unroll
    for (int i = 0; i < 4; i++)
        tile[threadIdx.y + i * 8][threadIdx.x] = wo[(o0 + threadIdx.y + i * 8) * 256 + c0 + threadIdx.x];
    __syncthreads();
#pragma unroll
    for (int i = 0; i < 4; i++)
        g_woT[(c0 + threadIdx.y + i * 8) * 256 + o0 + threadIdx.x] =
            tile[threadIdx.x][threadIdx.y + i * 8];
}

// ---------------- 2) conv via mma.sync, CTA = 64px x 256oc, warp = 32px x 64oc ----
// grid (16 pxtiles, 3 p, 8 b), block 256 (8 warps = 2m x 4n)
__global__ void __launch_bounds__(256) conv_mma_kernel() {
    const int nt  = blockIdx.x;
    const int p   = blockIdx.y;
    const int b   = blockIdx.z;
    const int tid = threadIdx.x, warp = tid >> 5, lane = tid & 31;
    const int wm = warp & 1, wn = warp >> 1;
    const int g = lane >> 2, t = lane & 3;
    const int px_warp = nt * 64 + wm * 32;

    float acc[2][8][4];
#pragma unroll
    for (int mt = 0; mt < 2; mt++)
#pragma unroll
        for (int n8 = 0; n8 < 8; n8++)
#pragma unroll
            for (int r = 0; r < 4; r++) acc[mt][n8][r] = 0.f;

    for (int tap = 0; tap < 9; tap++) {
        const int ky = tap / 3, kx = tap - ky * 3;
        for (int kc = 0; kc < 16; kc++) {
            // A fragments (X^T), both splits
            uint32_t afr[2][2][4];
#pragma unroll
            for (int mt = 0; mt < 2; mt++) {
                const int px  = px_warp + mt * 16 + g;
                const int y   = (px >> 5) + ky;
                const int x   = (px & 31) + kx;
                const int ic0 = kc * 16 + t * 2;
#pragma unroll
                for (int sp = 0; sp < 2; sp++) {
                    const __nv_bfloat16* xp =
                        g_xbfT + (((b * 2 + sp) * 34 + y) * 34 + x) * 256 + ic0;
                    afr[sp][mt][0] = *reinterpret_cast<const uint32_t*>(xp);
                    afr[sp][mt][2] = *reinterpret_cast<const uint32_t*>(xp + 8);
                    afr[sp][mt][1] = *reinterpret_cast<const uint32_t*>(xp + 2048);      // px+8
                    afr[sp][mt][3] = *reinterpret_cast<const uint32_t*>(xp + 2048 + 8);
                }
            }
            // B fragments (W, prepped), both splits, 8 n-tiles = 64 oc per warp
            uint32_t bfr[2][8][2];
#pragma unroll
            for (int sp = 0; sp < 2; sp++) {
                const ull* wb = reinterpret_cast<const ull*>(g_wfragB)
                    + ((((p * 9 + tap) * 2 + sp) * 16 + kc) * 32) * 32 + lane;
#pragma unroll
                for (int n8 = 0; n8 < 8; n8++) {
                    ull v = wb[(wn * 8 + n8) * 32];
                    bfr[sp][n8][0] = (uint32_t)v;
                    bfr[sp][n8][1] = (uint32_t)(v >> 32);
                }
            }
            // 3 split combos: (w_hi,x_hi), (w_hi,x_lo), (w_lo,x_hi)
#pragma unroll
            for (int combo = 0; combo < 3; combo++) {
                const int ws = combo >> 1, xs = combo & 1;
#pragma unroll
                for (int mt = 0; mt < 2; mt++)
#pragma unroll
                    for (int n8 = 0; n8 < 8; n8++)
                        mma16816(acc[mt][n8], afr[xs][mt], bfr[ws][n8]);
            }
        }
    }

    // epilogue: scatter D to g_act [oc][px], GN partial sums
    float s = 0.f, sq = 0.f;
#pragma unroll
    for (int mt = 0; mt < 2; mt++)
#pragma unroll
        for (int n8 = 0; n8 < 8; n8++)
#pragma unroll
            for (int r = 0; r < 4; r++) {
                float v  = acc[mt][n8][r];
                int   px = px_warp + mt * 16 + g + ((r >> 1) << 3);
                int   oc = wn * 64 + n8 * 8 + t * 2 + (r & 1);
                g_act[p][(b * 256 + oc) * 1024 + px] = v;
                s += v; sq += v * v;
            }
    __shared__ float red[512];
    red[tid] = s; red[tid + 256] = sq;
    __syncthreads();
    for (int st = 128; st > 0; st >>= 1) {
        if (tid < st) { red[tid] += red[tid + st]; red[tid + 256] += red[tid + 256 + st]; }
        __syncthreads();
    }
    if (tid == 0) {
        g_part[p][b][nt][0] = red[0];
        g_part[p][b][nt][1] = red[256];
    }
}

// ---------------- 3) GroupNorm(1) + exact GELU (16-wide partials) ----------------
__global__ void gn_gelu_kernel(const float* __restrict__ gq, const float* __restrict__ bq,
                               const float* __restrict__ gk, const float* __restrict__ bk,
                               const float* __restrict__ gv, const float* __restrict__ bv) {
    const int chunk = blockIdx.x;
    const int b     = blockIdx.y;
    const int p     = blockIdx.z;
    const float* gg = (p == 0) ? gq : (p == 1) ? gk : gv;
    const float* bb = (p == 0) ? bq : (p == 1) ? bk : bv;

    __shared__ float s_mu, s_rs;
    if (threadIdx.x < 16) {
        float s  = g_part[p][b][threadIdx.x][0];
        float sq = g_part[p][b][threadIdx.x][1];
#pragma unroll
        for (int o = 8; o > 0; o >>= 1) {
            s  += __shfl_down_sync(0x0000ffffu, s,  o);
            sq += __shfl_down_sync(0x0000ffffu, sq, o);
        }
        if (threadIdx.x == 0) {
            float mu  = s / (float)NPER;
            float var = sq / (float)NPER - mu * mu;
            s_mu = mu;
            s_rs = rsqrtf(var + 1e-6f);
        }
    }
    __syncthreads();
    const float mu = s_mu, rs = s_rs;

    float* base = &g_act[p][b * NPER + chunk * 32768];
    for (int i = threadIdx.x; i < 8192; i += 256) {
        float4 v = reinterpret_cast<float4*>(base)[i];
        int c = (chunk * 32768 + i * 4) >> 10;
        float gc = gg[c], bc = bb[c];
        float t0 = (v.x - mu) * rs * gc + bc;
        float t1 = (v.y - mu) * rs * gc + bc;
        float t2 = (v.z - mu) * rs * gc + bc;
        float t3 = (v.w - mu) * rs * gc + bc;
        v.x = 0.5f * t0 * (1.0f + erff(t0 * 0.70710678118654752f));
        v.y = 0.5f * t1 * (1.0f + erff(t1 * 0.70710678118654752f));
        v.z = 0.5f * t2 * (1.0f + erff(t2 * 0.70710678118654752f));
        v.w = 0.5f * t3 * (1.0f + erff(t3 * 0.70710678118654752f));
        reinterpret_cast<float4*>(base)[i] = v;
    }
}

// ---------------- 4) flash attention (R6 version) ----------------
__global__ void __launch_bounds__(128, 4) attn_kernel(const float* __restrict__ bias_table) {
    const int q0  = blockIdx.x * 128;
    const int h   = blockIdx.y;
    const int b   = blockIdx.z;
    const int tid = threadIdx.x;

    __shared__ __align__(16) float s_bias[BIASN + 3];
    __shared__ __align__(16) float s_q[32 * 128];
    __shared__ __align__(16) float s_k[32 * 64];
    __shared__ __align__(16) ull   s_v2T[64 * 18];

    for (int i = tid; i < BIASN; i += 128)
        s_bias[i] = bias_table[i * HEADS + h];

    const float* aq = &g_act[0][(b * 256 + h * DHEAD) * NTOK];
    const float* ak = &g_act[1][(b * 256 + h * DHEAD) * NTOK];
    const float* av = &g_act[2][(b * 256 + h * DHEAD) * NTOK];

    const int qi = q0 + tid;
#pragma unroll
    for (int d = 0; d < DHEAD; d++)
        s_q[d * 128 + tid] = aq[d * NTOK + qi];

    const int yi = qi >> 5, xi = qi & 31;

    float m = -1e30f, l = 0.f;
    ull o2[16];
#pragma unroll
    for (int d2 = 0; d2 < 16; d2++) o2[d2] = 0ull;

    for (int kt = 0; kt < 16; kt++) {
        const int k0 = kt * 64;
        __syncthreads();
        for (int e = tid; e < 1024; e += 128) {
            int d2 = e >> 6, j = e & 63;
            float v0 = av[(2 * d2) * NTOK + k0 + j];
            float v1 = av[(2 * d2 + 1) * NTOK + k0 + j];
            s_k[(2 * d2) * 64 + j]     = ak[(2 * d2) * NTOK + k0 + j];
            s_k[(2 * d2 + 1) * 64 + j] = ak[(2 * d2 + 1) * NTOK + k0 + j];
            s_v2T[j * 18 + d2] = pack2(v0, v1);
        }
        __syncthreads();

        for (int sub = 0; sub < 2; sub++) {
            const int j0 = sub * 32;
            ull s2[16];
#pragma unroll
            for (int pp = 0; pp < 16; pp++) {
                int kg = k0 + j0 + 2 * pp;
                int yj = kg >> 5, xj = kg & 31;
                int idx0 = (yi - yj + 31) * 63 + (xi - xj + 31);
                int kg1 = kg + 1;
                int yj1 = kg1 >> 5, xj1 = kg1 & 31;
                int idx1 = (yi - yj1 + 31) * 63 + (xi - xj1 + 31);
                s2[pp] = pack2(s_bias[idx0], s_bias[idx1]);
            }
#pragma unroll
            for (int d = 0; d < DHEAD; d++) {
                float qd = s_q[d * 128 + tid];
                const ull q2d = pack2(qd, qd);
                const ulonglong2* krow =
                    reinterpret_cast<const ulonglong2*>(&s_k[d * 64 + j0]);
#pragma unroll
                for (int pq = 0; pq < 8; pq++) {
                    ulonglong2 kk = krow[pq];
                    ffma2(s2[2 * pq],     q2d, kk.x);
                    ffma2(s2[2 * pq + 1], q2d, kk.y);
                }
            }
            float mn = m;
#pragma unroll
            for (int pp = 0; pp < 16; pp++)
                mn = fmaxf(mn, fmaxf(lo2(s2[pp]), hi2(s2[pp])));
            const float scale = __expf(m - mn);
            m = mn;
            ull ls2 = 0ull;
#pragma unroll
            for (int pp = 0; pp < 16; pp++) {
                float ea = __expf(lo2(s2[pp]) - mn);
                float eb = __expf(hi2(s2[pp]) - mn);
                s2[pp] = pack2(ea, eb);
                ls2 = add2(ls2, s2[pp]);
            }
            l = l * scale + lo2(ls2) + hi2(ls2);
            const ull sc2 = pack2(scale, scale);
#pragma unroll
            for (int d2 = 0; d2 < 16; d2++) o2[d2] = mul2(o2[d2], sc2);
#pragma unroll
            for (int jj = 0; jj < 32; jj++) {
                float pj = (jj & 1) ? hi2(s2[jj >> 1]) : lo2(s2[jj >> 1]);
                ull pj2 = pack2(pj, pj);
                const ulonglong2* vrow =
                    reinterpret_cast<const ulonglong2*>(&s_v2T[(j0 + jj) * 18]);
#pragma unroll
                for (int q8 = 0; q8 < 8; q8++) {
                    ulonglong2 vv = vrow[q8];
                    ffma2(o2[2 * q8],     pj2, vv.x);
                    ffma2(o2[2 * q8 + 1], pj2, vv.y);
                }
            }
        }
    }

    const float inv = 1.f / l;
    float* ao = &g_attn[(b * 256 + h * DHEAD) * NTOK];
#pragma unroll
    for (int d2 = 0; d2 < 16; d2++) {
        ao[(2 * d2) * NTOK + qi]     = lo2(o2[d2]) * inv;
        ao[(2 * d2 + 1) * NTOK + qi] = hi2(o2[d2]) * inv;
    }
}

// ---------------- 5) 1x1 output projection ----------------
__global__ void outproj_kernel(const float* __restrict__ bo, float* __restrict__ out) {
    const int nt = blockIdx.x;
    const int b  = blockIdx.y;
    const int oc = threadIdx.x;

    __shared__ __align__(16) float s_a[256 * 32];
    for (int e = oc; e < 8192; e += 256) {
        int c = e >> 5, px = e & 31;
        s_a[e] = g_attn[(b * 256 + c) * NTOK + nt * 32 + px];
    }
    __syncthreads();

    ull acc[16];
#pragma unroll
    for (int p = 0; p < 16; p++) acc[p] = 0ull;

    for (int c = 0; c < 256; c++) {
        float wv = g_woT[c * 256 + oc];
        ull w2 = pack2(wv, wv);
        const ulonglong2* arow2 = reinterpret_cast<const ulonglong2*>(&s_a[c * 32]);
#pragma unroll
        for (int p8 = 0; p8 < 8; p8++) {
            ulonglong2 vv = arow2[p8];
            ffma2(acc[2 * p8],     w2, vv.x);
            ffma2(acc[2 * p8 + 1], w2, vv.y);
        }
    }

    const float bb = bo[oc];
    float* op = out + (b * 256 + oc) * NTOK + nt * 32;
#pragma unroll
    for (int p = 0; p < 16; p += 2) {
        float4 v4 = make_float4(lo2(acc[p]) + bb,     hi2(acc[p]) + bb,
                                lo2(acc[p + 1]) + bb, hi2(acc[p + 1]) + bb);
        *reinterpret_cast<float4*>(op + 2 * p) = v4;
    }
}

// ---------------- launch ----------------
extern "C" void kernel_launch(void* const* d_in, const int* in_sizes, int n_in,
                              void* d_out, int out_size) {
    const float* x  = (const float*)d_in[0];
    const float* wq = (const float*)d_in[1];
    const float* wk = (const float*)d_in[2];
    const float* wv = (const float*)d_in[3];
    const float* gq = (const float*)d_in[4];
    const float* bq = (const float*)d_in[5];
    const float* gk = (const float*)d_in[6];
    const float* bk = (const float*)d_in[7];
    const float* gv = (const float*)d_in[8];
    const float* bv = (const float*)d_in[9];
    const float* bt = (const float*)d_in[10];
    const float* wo = (const float*)d_in[11];
    const float* bo = (const float*)d_in[12];
    float* out = (float*)d_out;

    prep_w_kernel<<<dim3(64, 9, 3), 256>>>(wq, wk, wv);
    prep_x_kernel<<<dim3(34, BATCH), 256>>>(x);
    transpose_wo_kernel<<<dim3(8, 8), dim3(32, 8)>>>(wo);
    conv_mma_kernel<<<dim3(16, 3, BATCH), 256>>>();
    gn_gelu_kernel<<<dim3(8, BATCH, 3), 256>>>(gq, bq, gk, bk, gv, bv);
    attn_kernel<<<dim3(8, HEADS, BATCH), 128>>>(bt);
    outproj_kernel<<<dim3(32, BATCH), 256>>>(bo, out);
}

// round 11
// speedup vs baseline: 1.6864x; 1.0488x over previous
#include <cuda_runtime.h>
#include <cuda_bf16.h>
#include <cstdint>
#include <cstring>

typedef unsigned long long ull;

// Problem constants
#define BATCH 8
#define CHAN  256
#define HEADS 8
#define DHEAD 32
#define NTOK  1024
#define NPER  262144
#define BIASN 3969

// ---------------- scratch ----------------
// W fragments: [p][tap][split][kc(16)][npair(16)][lane(32)][2 frag x 8B]
__device__ __align__(16) __nv_bfloat16 g_wfragB[3*9*2*16*32*32*4];
// X transposed+padded bf16 split: [b][split][y(34)][x(34)][c(256)]
__device__ __align__(16) __nv_bfloat16 g_xbfT[8*2*34*34*256];
__device__ __align__(16) float g_woT[256*256];                 // [c][o]
__device__ __align__(16) float g_act[3][BATCH*NPER];           // conv->gelu activations
__device__ __align__(16) float g_part[3][BATCH][16][2];        // GN partials (16 ntiles)
__device__ __align__(16) float g_attn[BATCH*NPER];

// ---------------- f32x2 helpers ----------------
__device__ __forceinline__ void ffma2(ull& d, ull a, ull b) {
    asm("fma.rn.f32x2 %0, %1, %2, %0;" : "+l"(d) : "l"(a), "l"(b));
}
__device__ __forceinline__ ull add2(ull a, ull b) {
    ull r; asm("add.rn.f32x2 %0, %1, %2;" : "=l"(r) : "l"(a), "l"(b)); return r;
}
__device__ __forceinline__ ull mul2(ull a, ull b) {
    ull r; asm("mul.rn.f32x2 %0, %1, %2;" : "=l"(r) : "l"(a), "l"(b)); return r;
}
__device__ __forceinline__ ull pack2(float a, float b) {
    ull u; asm("mov.b64 %0, {%1,%2};" : "=l"(u) : "f"(a), "f"(b)); return u;
}
__device__ __forceinline__ float lo2(ull u) { return __int_as_float((int)(unsigned)u); }
__device__ __forceinline__ float hi2(ull u) { return __int_as_float((int)(u >> 32)); }

// ---------------- warp mma helper (bf16, fp32 accum) ----------------
__device__ __forceinline__ void mma16816(float* c, const uint32_t* a, const uint32_t* b) {
    asm volatile("mma.sync.aligned.m16n8k16.row.col.f32.bf16.bf16.f32 "
        "{%0,%1,%2,%3}, {%4,%5,%6,%7}, {%8,%9}, {%0,%1,%2,%3};"
        : "+f"(c[0]), "+f"(c[1]), "+f"(c[2]), "+f"(c[3])
        : "r"(a[0]), "r"(a[1]), "r"(a[2]), "r"(a[3]), "r"(b[0]), "r"(b[1]));
}

// ---------------- 1a) weight prep, ic-permuted fragment order ----------------
// grid (64, 9, 3), block 256.
// Logical k {2t,2t+1,2t+8,2t+9} mapped to physical ic {4t,4t+1,4t+2,4t+3}.
// Frag values: b0 = phys(4t,4t+1), b1 = phys(4t+2,4t+3).
__global__ void prep_w_kernel(const float* __restrict__ wq,
                              const float* __restrict__ wk,
                              const float* __restrict__ wv) {
    const int sub = threadIdx.x >> 5, lane = threadIdx.x & 31;
    const int fi = blockIdx.x * 8 + sub;         // 0..511 = (kc, ntile)
    const int kc = fi >> 5, ntile = fi & 31;
    const int tap = blockIdx.y, p = blockIdx.z;
    const float* w = (p == 0) ? wq : (p == 1) ? wk : wv;
    const int t = lane & 3, g = lane >> 2;
    const int oc = ntile * 8 + g;
    const int k0 = kc * 16 + t * 4;
    const int npair = ntile >> 1, half = ntile & 1;

    float v0 = w[oc * 2304 + (k0    ) * 9 + tap];
    float v1 = w[oc * 2304 + (k0 + 1) * 9 + tap];
    float v2 = w[oc * 2304 + (k0 + 2) * 9 + tap];
    float v3 = w[oc * 2304 + (k0 + 3) * 9 + tap];

    __nv_bfloat16 h0 = __float2bfloat16(v0), h1 = __float2bfloat16(v1);
    __nv_bfloat16 h2 = __float2bfloat16(v2), h3 = __float2bfloat16(v3);
    __nv_bfloat16 l0 = __float2bfloat16(v0 - __bfloat162float(h0));
    __nv_bfloat16 l1 = __float2bfloat16(v1 - __bfloat162float(h1));
    __nv_bfloat16 l2 = __float2bfloat16(v2 - __bfloat162float(h2));
    __nv_bfloat16 l3 = __float2bfloat16(v3 - __bfloat162float(h3));

    // 8B frag slot index: [sp=0][kc][npair][lane][half]
    int slot = (((((p * 9 + tap) * 2 + 0) * 16 + kc) * 16 + npair) * 32 + lane) * 2 + half;
    __nv_bfloat16* dh = g_wfragB + slot * 4;
    dh[0] = h0; dh[1] = h1; dh[2] = h2; dh[3] = h3;
    __nv_bfloat16* dl = dh + 16 * 32 * 32 * 4;   // split stride in bf16
    dl[0] = l0; dl[1] = l1; dl[2] = l2; dl[3] = l3;
}

// ---------------- 1b) input transpose + pad + bf16-split ----------------
__global__ void prep_x_kernel(const float* __restrict__ x) {
    const int y = blockIdx.x, b = blockIdx.y, c = threadIdx.x;
    __shared__ float s_t[256][33];
    const bool rowvalid = (y >= 1 && y <= 32);
    if (rowvalid) {
        const float* src = x + ((b * 256 + c) * 32 + (y - 1)) * 32;
#pragma unroll
        for (int i = 0; i < 8; i++) {
            float4 v = reinterpret_cast<const float4*>(src)[i];
            s_t[c][i * 4 + 0] = v.x; s_t[c][i * 4 + 1] = v.y;
            s_t[c][i * 4 + 2] = v.z; s_t[c][i * 4 + 3] = v.w;
        }
    }
    __syncthreads();
    for (int xx = 0; xx < 34; xx++) {
        float v = (rowvalid && xx >= 1 && xx <= 32) ? s_t[c][xx - 1] : 0.f;
        __nv_bfloat16 hi = __float2bfloat16(v);
        __nv_bfloat16 lo = __float2bfloat16(v - __bfloat162float(hi));
        int base = (((b * 2) * 34 + y) * 34 + xx) * 256 + c;
        g_xbfT[base]              = hi;
        g_xbfT[base + 34*34*256]  = lo;
    }
}

// ---------------- 1c) wo transpose ----------------
__global__ void transpose_wo_kernel(const float* __restrict__ wo) {
    __shared__ float tile[32][33];
    const int c0 = blockIdx.x * 32, o0 = blockIdx.y * 32;
#pragma unroll
    for (int i = 0; i < 4; i++)
        tile[threadIdx.y + i * 8][threadIdx.x] = wo[(o0 + threadIdx.y + i * 8) * 256 + c0 + threadIdx.x];
    __syncthreads();
#pragma unroll
    for (int i = 0; i < 4; i++)
        g_woT[(c0 + threadIdx.y + i * 8) * 256 + o0 + threadIdx.x] =
            tile[threadIdx.x][threadIdx.y + i * 8];
}

// ---------------- 2) conv via mma.sync, CTA = 64px x 256oc, warp = 32px x 64oc ----
// grid (16 pxtiles, 3 p, 8 b), block 256 (8 warps = 2m x 4n)
// A loads: 8 LDG.64 (ic-permuted contiguous); B loads: 8 LDG.128 (pair-packed frags)
__global__ void __launch_bounds__(256) conv_mma_kernel() {
    const int nt  = blockIdx.x;
    const int p   = blockIdx.y;
    const int b   = blockIdx.z;
    const int tid = threadIdx.x, warp = tid >> 5, lane = tid & 31;
    const int wm = warp & 1, wn = warp >> 1;
    const int g = lane >> 2, t = lane & 3;
    const int px_warp = nt * 64 + wm * 32;

    float acc[2][8][4];
#pragma unroll
    for (int mt = 0; mt < 2; mt++)
#pragma unroll
        for (int n8 = 0; n8 < 8; n8++)
#pragma unroll
            for (int r = 0; r < 4; r++) acc[mt][n8][r] = 0.f;

    const ulonglong2* wfrag16 = reinterpret_cast<const ulonglong2*>(g_wfragB);

    for (int tap = 0; tap < 9; tap++) {
        const int ky = tap / 3, kx = tap - ky * 3;
        for (int kc = 0; kc < 16; kc++) {
            // A fragments (X^T), both splits: 2 LDG.64 per (mt,sp)
            uint32_t afr[2][2][4];
#pragma unroll
            for (int mt = 0; mt < 2; mt++) {
                const int px  = px_warp + mt * 16 + g;
                const int y   = (px >> 5) + ky;
                const int x   = (px & 31) + kx;
                const int ic0 = kc * 16 + t * 4;
#pragma unroll
                for (int sp = 0; sp < 2; sp++) {
                    const __nv_bfloat16* xp =
                        g_xbfT + (((b * 2 + sp) * 34 + y) * 34 + x) * 256 + ic0;
                    ull v0 = *reinterpret_cast<const ull*>(xp);
                    ull v1 = *reinterpret_cast<const ull*>(xp + 2048);   // px+8 row
                    afr[sp][mt][0] = (uint32_t)v0;
                    afr[sp][mt][2] = (uint32_t)(v0 >> 32);
                    afr[sp][mt][1] = (uint32_t)v1;
                    afr[sp][mt][3] = (uint32_t)(v1 >> 32);
                }
            }
            // B fragments: 4 LDG.128 per sp (2 frags each)
            uint32_t bfr[2][8][2];
#pragma unroll
            for (int sp = 0; sp < 2; sp++) {
                const ulonglong2* wb = wfrag16 +
                    ((((p * 9 + tap) * 2 + sp) * 16 + kc) * 16) * 32 + lane;
#pragma unroll
                for (int n4 = 0; n4 < 4; n4++) {
                    ulonglong2 v = wb[(wn * 4 + n4) * 32];
                    bfr[sp][2 * n4][0]     = (uint32_t)v.x;
                    bfr[sp][2 * n4][1]     = (uint32_t)(v.x >> 32);
                    bfr[sp][2 * n4 + 1][0] = (uint32_t)v.y;
                    bfr[sp][2 * n4 + 1][1] = (uint32_t)(v.y >> 32);
                }
            }
            // 3 split combos: (w_hi,x_hi), (w_hi,x_lo), (w_lo,x_hi)
#pragma unroll
            for (int combo = 0; combo < 3; combo++) {
                const int ws = combo >> 1, xs = combo & 1;
#pragma unroll
                for (int mt = 0; mt < 2; mt++)
#pragma unroll
                    for (int n8 = 0; n8 < 8; n8++)
                        mma16816(acc[mt][n8], afr[xs][mt], bfr[ws][n8]);
            }
        }
    }

    // epilogue: scatter D to g_act [oc][px], GN partial sums
    float s = 0.f, sq = 0.f;
#pragma unroll
    for (int mt = 0; mt < 2; mt++)
#pragma unroll
        for (int n8 = 0; n8 < 8; n8++)
#pragma unroll
            for (int r = 0; r < 4; r++) {
                float v  = acc[mt][n8][r];
                int   px = px_warp + mt * 16 + g + ((r >> 1) << 3);
                int   oc = wn * 64 + n8 * 8 + t * 2 + (r & 1);
                g_act[p][(b * 256 + oc) * 1024 + px] = v;
                s += v; sq += v * v;
            }
    __shared__ float red[512];
    red[tid] = s; red[tid + 256] = sq;
    __syncthreads();
    for (int st = 128; st > 0; st >>= 1) {
        if (tid < st) { red[tid] += red[tid + st]; red[tid + 256] += red[tid + 256 + st]; }
        __syncthreads();
    }
    if (tid == 0) {
        g_part[p][b][nt][0] = red[0];
        g_part[p][b][nt][1] = red[256];
    }
}

// ---------------- 3) GroupNorm(1) + exact GELU (16-wide partials) ----------------
__global__ void gn_gelu_kernel(const float* __restrict__ gq, const float* __restrict__ bq,
                               const float* __restrict__ gk, const float* __restrict__ bk,
                               const float* __restrict__ gv, const float* __restrict__ bv) {
    const int chunk = blockIdx.x;
    const int b     = blockIdx.y;
    const int p     = blockIdx.z;
    const float* gg = (p == 0) ? gq : (p == 1) ? gk : gv;
    const float* bb = (p == 0) ? bq : (p == 1) ? bk : bv;

    __shared__ float s_mu, s_rs;
    if (threadIdx.x < 16) {
        float s  = g_part[p][b][threadIdx.x][0];
        float sq = g_part[p][b][threadIdx.x][1];
#pragma unroll
        for (int o = 8; o > 0; o >>= 1) {
            s  += __shfl_down_sync(0x0000ffffu, s,  o);
            sq += __shfl_down_sync(0x0000ffffu, sq, o);
        }
        if (threadIdx.x == 0) {
            float mu  = s / (float)NPER;
            float var = sq / (float)NPER - mu * mu;
            s_mu = mu;
            s_rs = rsqrtf(var + 1e-6f);
        }
    }
    __syncthreads();
    const float mu = s_mu, rs = s_rs;

    float* base = &g_act[p][b * NPER + chunk * 32768];
    for (int i = threadIdx.x; i < 8192; i += 256) {
        float4 v = reinterpret_cast<float4*>(base)[i];
        int c = (chunk * 32768 + i * 4) >> 10;
        float gc = gg[c], bc = bb[c];
        float t0 = (v.x - mu) * rs * gc + bc;
        float t1 = (v.y - mu) * rs * gc + bc;
        float t2 = (v.z - mu) * rs * gc + bc;
        float t3 = (v.w - mu) * rs * gc + bc;
        v.x = 0.5f * t0 * (1.0f + erff(t0 * 0.70710678118654752f));
        v.y = 0.5f * t1 * (1.0f + erff(t1 * 0.70710678118654752f));
        v.z = 0.5f * t2 * (1.0f + erff(t2 * 0.70710678118654752f));
        v.w = 0.5f * t3 * (1.0f + erff(t3 * 0.70710678118654752f));
        reinterpret_cast<float4*>(base)[i] = v;
    }
}

// ---------------- 4) flash attention (R6 version) ----------------
__global__ void __launch_bounds__(128, 4) attn_kernel(const float* __restrict__ bias_table) {
    const int q0  = blockIdx.x * 128;
    const int h   = blockIdx.y;
    const int b   = blockIdx.z;
    const int tid = threadIdx.x;

    __shared__ __align__(16) float s_bias[BIASN + 3];
    __shared__ __align__(16) float s_q[32 * 128];
    __shared__ __align__(16) float s_k[32 * 64];
    __shared__ __align__(16) ull   s_v2T[64 * 18];

    for (int i = tid; i < BIASN; i += 128)
        s_bias[i] = bias_table[i * HEADS + h];

    const float* aq = &g_act[0][(b * 256 + h * DHEAD) * NTOK];
    const float* ak = &g_act[1][(b * 256 + h * DHEAD) * NTOK];
    const float* av = &g_act[2][(b * 256 + h * DHEAD) * NTOK];

    const int qi = q0 + tid;
#pragma unroll
    for (int d = 0; d < DHEAD; d++)
        s_q[d * 128 + tid] = aq[d * NTOK + qi];

    const int yi = qi >> 5, xi = qi & 31;

    float m = -1e30f, l = 0.f;
    ull o2[16];
#pragma unroll
    for (int d2 = 0; d2 < 16; d2++) o2[d2] = 0ull;

    for (int kt = 0; kt < 16; kt++) {
        const int k0 = kt * 64;
        __syncthreads();
        for (int e = tid; e < 1024; e += 128) {
            int d2 = e >> 6, j = e & 63;
            float v0 = av[(2 * d2) * NTOK + k0 + j];
            float v1 = av[(2 * d2 + 1) * NTOK + k0 + j];
            s_k[(2 * d2) * 64 + j]     = ak[(2 * d2) * NTOK + k0 + j];
            s_k[(2 * d2 + 1) * 64 + j] = ak[(2 * d2 + 1) * NTOK + k0 + j];
            s_v2T[j * 18 + d2] = pack2(v0, v1);
        }
        __syncthreads();

        for (int sub = 0; sub < 2; sub++) {
            const int j0 = sub * 32;
            ull s2[16];
#pragma unroll
            for (int pp = 0; pp < 16; pp++) {
                int kg = k0 + j0 + 2 * pp;
                int yj = kg >> 5, xj = kg & 31;
                int idx0 = (yi - yj + 31) * 63 + (xi - xj + 31);
                int kg1 = kg + 1;
                int yj1 = kg1 >> 5, xj1 = kg1 & 31;
                int idx1 = (yi - yj1 + 31) * 63 + (xi - xj1 + 31);
                s2[pp] = pack2(s_bias[idx0], s_bias[idx1]);
            }
#pragma unroll
            for (int d = 0; d < DHEAD; d++) {
                float qd = s_q[d * 128 + tid];
                const ull q2d = pack2(qd, qd);
                const ulonglong2* krow =
                    reinterpret_cast<const ulonglong2*>(&s_k[d * 64 + j0]);
#pragma unroll
                for (int pq = 0; pq < 8; pq++) {
                    ulonglong2 kk = krow[pq];
                    ffma2(s2[2 * pq],     q2d, kk.x);
                    ffma2(s2[2 * pq + 1], q2d, kk.y);
                }
            }
            float mn = m;
#pragma unroll
            for (int pp = 0; pp < 16; pp++)
                mn = fmaxf(mn, fmaxf(lo2(s2[pp]), hi2(s2[pp])));
            const float scale = __expf(m - mn);
            m = mn;
            ull ls2 = 0ull;
#pragma unroll
            for (int pp = 0; pp < 16; pp++) {
                float ea = __expf(lo2(s2[pp]) - mn);
                float eb = __expf(hi2(s2[pp]) - mn);
                s2[pp] = pack2(ea, eb);
                ls2 = add2(ls2, s2[pp]);
            }
            l = l * scale + lo2(ls2) + hi2(ls2);
            const ull sc2 = pack2(scale, scale);
#pragma unroll
            for (int d2 = 0; d2 < 16; d2++) o2[d2] = mul2(o2[d2], sc2);
#pragma unroll
            for (int jj = 0; jj < 32; jj++) {
                float pj = (jj & 1) ? hi2(s2[jj >> 1]) : lo2(s2[jj >> 1]);
                ull pj2 = pack2(pj, pj);
                const ulonglong2* vrow =
                    reinterpret_cast<const ulonglong2*>(&s_v2T[(j0 + jj) * 18]);
#pragma unroll
                for (int q8 = 0; q8 < 8; q8++) {
                    ulonglong2 vv = vrow[q8];
                    ffma2(o2[2 * q8],     pj2, vv.x);
                    ffma2(o2[2 * q8 + 1], pj2, vv.y);
                }
            }
        }
    }

    const float inv = 1.f / l;
    float* ao = &g_attn[(b * 256 + h * DHEAD) * NTOK];
#pragma unroll
    for (int d2 = 0; d2 < 16; d2++) {
        ao[(2 * d2) * NTOK + qi]     = lo2(o2[d2]) * inv;
        ao[(2 * d2 + 1) * NTOK + qi] = hi2(o2[d2]) * inv;
    }
}

// ---------------- 5) 1x1 output projection ----------------
__global__ void outproj_kernel(const float* __restrict__ bo, float* __restrict__ out) {
    const int nt = blockIdx.x;
    const int b  = blockIdx.y;
    const int oc = threadIdx.x;

    __shared__ __align__(16) float s_a[256 * 32];
    for (int e = oc; e < 8192; e += 256) {
        int c = e >> 5, px = e & 31;
        s_a[e] = g_attn[(b * 256 + c) * NTOK + nt * 32 + px];
    }
    __syncthreads();

    ull acc[16];
#pragma unroll
    for (int p = 0; p < 16; p++) acc[p] = 0ull;

    for (int c = 0; c < 256; c++) {
        float wv = g_woT[c * 256 + oc];
        ull w2 = pack2(wv, wv);
        const ulonglong2* arow2 = reinterpret_cast<const ulonglong2*>(&s_a[c * 32]);
#pragma unroll
        for (int p8 = 0; p8 < 8; p8++) {
            ulonglong2 vv = arow2[p8];
            ffma2(acc[2 * p8],     w2, vv.x);
            ffma2(acc[2 * p8 + 1], w2, vv.y);
        }
    }

    const float bb = bo[oc];
    float* op = out + (b * 256 + oc) * NTOK + nt * 32;
#pragma unroll
    for (int p = 0; p < 16; p += 2) {
        float4 v4 = make_float4(lo2(acc[p]) + bb,     hi2(acc[p]) + bb,
                                lo2(acc[p + 1]) + bb, hi2(acc[p + 1]) + bb);
        *reinterpret_cast<float4*>(op + 2 * p) = v4;
    }
}

// ---------------- launch ----------------
extern "C" void kernel_launch(void* const* d_in, const int* in_sizes, int n_in,
                              void* d_out, int out_size) {
    const float* x  = (const float*)d_in[0];
    const float* wq = (const float*)d_in[1];
    const float* wk = (const float*)d_in[2];
    const float* wv = (const float*)d_in[3];
    const float* gq = (const float*)d_in[4];
    const float* bq = (const float*)d_in[5];
    const float* gk = (const float*)d_in[6];
    const float* bk = (const float*)d_in[7];
    const float* gv = (const float*)d_in[8];
    const float* bv = (const float*)d_in[9];
    const float* bt = (const float*)d_in[10];
    const float* wo = (const float*)d_in[11];
    const float* bo = (const float*)d_in[12];
    float* out = (float*)d_out;

    prep_w_kernel<<<dim3(64, 9, 3), 256>>>(wq, wk, wv);
    prep_x_kernel<<<dim3(34, BATCH), 256>>>(x);
    transpose_wo_kernel<<<dim3(8, 8), dim3(32, 8)>>>(wo);
    conv_mma_kernel<<<dim3(16, 3, BATCH), 256>>>();
    gn_gelu_kernel<<<dim3(8, BATCH, 3), 256>>>(gq, bq, gk, bk, gv, bv);
    attn_kernel<<<dim3(8, HEADS, BATCH), 128>>>(bt);
    outproj_kernel<<<dim3(32, BATCH), 256>>>(bo, out);
}

// round 12
// speedup vs baseline: 1.9968x; 1.1841x over previous
#include <cuda_runtime.h>
#include <cuda_bf16.h>
#include <cstdint>
#include <cstring>

typedef unsigned long long ull;

// Problem constants
#define BATCH 8
#define CHAN  256
#define HEADS 8
#define DHEAD 32
#define NTOK  1024
#define NPER  262144
#define BIASN 3969

// ---------------- scratch ----------------
// W fragments: [p][tap][split][kc(16)][npair(16)][lane(32)][2 frag x 8B]
__device__ __align__(16) __nv_bfloat16 g_wfragB[3*9*2*16*32*32*4];
// X transposed+padded bf16 split: [b][split][y(34)][x(34)][c(256)]
__device__ __align__(16) __nv_bfloat16 g_xbfT[8*2*34*34*256];
__device__ __align__(16) float g_woT[256*256];                 // [c][o]
__device__ __align__(16) float g_act[3][BATCH*NPER];           // conv->gelu activations
__device__ __align__(16) float g_part[3][BATCH][16][2];        // GN partials (16 ntiles)
__device__ __align__(16) float g_attn[BATCH*NPER];

// ---------------- f32x2 helpers ----------------
__device__ __forceinline__ void ffma2(ull& d, ull a, ull b) {
    asm("fma.rn.f32x2 %0, %1, %2, %0;" : "+l"(d) : "l"(a), "l"(b));
}
__device__ __forceinline__ ull pack2(float a, float b) {
    ull u; asm("mov.b64 %0, {%1,%2};" : "=l"(u) : "f"(a), "f"(b)); return u;
}
__device__ __forceinline__ float lo2(ull u) { return __int_as_float((int)(unsigned)u); }
__device__ __forceinline__ float hi2(ull u) { return __int_as_float((int)(u >> 32)); }

// ---------------- warp mma helper (bf16, fp32 accum) ----------------
__device__ __forceinline__ void mma16816(float* c, const uint32_t* a, const uint32_t* b) {
    asm volatile("mma.sync.aligned.m16n8k16.row.col.f32.bf16.bf16.f32 "
        "{%0,%1,%2,%3}, {%4,%5,%6,%7}, {%8,%9}, {%0,%1,%2,%3};"
        : "+f"(c[0]), "+f"(c[1]), "+f"(c[2]), "+f"(c[3])
        : "r"(a[0]), "r"(a[1]), "r"(a[2]), "r"(a[3]), "r"(b[0]), "r"(b[1]));
}

// split two f32 into bf16x2 hi-word and lo-word (element0 = low 16 bits)
__device__ __forceinline__ void split2(float v0, float v1, uint32_t& hi, uint32_t& lo) {
    __nv_bfloat16 h0 = __float2bfloat16(v0), h1 = __float2bfloat16(v1);
    __nv_bfloat16 l0 = __float2bfloat16(v0 - __bfloat162float(h0));
    __nv_bfloat16 l1 = __float2bfloat16(v1 - __bfloat162float(h1));
    __nv_bfloat162 ph; ph.x = h0; ph.y = h1;
    __nv_bfloat162 pl; pl.x = l0; pl.y = l1;
    hi = *reinterpret_cast<uint32_t*>(&ph);
    lo = *reinterpret_cast<uint32_t*>(&pl);
}

// ---------------- 1a) weight prep, ic-permuted fragment order ----------------
__global__ void prep_w_kernel(const float* __restrict__ wq,
                              const float* __restrict__ wk,
                              const float* __restrict__ wv) {
    const int sub = threadIdx.x >> 5, lane = threadIdx.x & 31;
    const int fi = blockIdx.x * 8 + sub;
    const int kc = fi >> 5, ntile = fi & 31;
    const int tap = blockIdx.y, p = blockIdx.z;
    const float* w = (p == 0) ? wq : (p == 1) ? wk : wv;
    const int t = lane & 3, g = lane >> 2;
    const int oc = ntile * 8 + g;
    const int k0 = kc * 16 + t * 4;
    const int npair = ntile >> 1, half = ntile & 1;

    float v0 = w[oc * 2304 + (k0    ) * 9 + tap];
    float v1 = w[oc * 2304 + (k0 + 1) * 9 + tap];
    float v2 = w[oc * 2304 + (k0 + 2) * 9 + tap];
    float v3 = w[oc * 2304 + (k0 + 3) * 9 + tap];

    __nv_bfloat16 h0 = __float2bfloat16(v0), h1 = __float2bfloat16(v1);
    __nv_bfloat16 h2 = __float2bfloat16(v2), h3 = __float2bfloat16(v3);
    __nv_bfloat16 l0 = __float2bfloat16(v0 - __bfloat162float(h0));
    __nv_bfloat16 l1 = __float2bfloat16(v1 - __bfloat162float(h1));
    __nv_bfloat16 l2 = __float2bfloat16(v2 - __bfloat162float(h2));
    __nv_bfloat16 l3 = __float2bfloat16(v3 - __bfloat162float(h3));

    int slot = (((((p * 9 + tap) * 2 + 0) * 16 + kc) * 16 + npair) * 32 + lane) * 2 + half;
    __nv_bfloat16* dh = g_wfragB + slot * 4;
    dh[0] = h0; dh[1] = h1; dh[2] = h2; dh[3] = h3;
    __nv_bfloat16* dl = dh + 16 * 32 * 32 * 4;
    dl[0] = l0; dl[1] = l1; dl[2] = l2; dl[3] = l3;
}

// ---------------- 1b) input transpose + pad + bf16-split ----------------
__global__ void prep_x_kernel(const float* __restrict__ x) {
    const int y = blockIdx.x, b = blockIdx.y, c = threadIdx.x;
    __shared__ float s_t[256][33];
    const bool rowvalid = (y >= 1 && y <= 32);
    if (rowvalid) {
        const float* src = x + ((b * 256 + c) * 32 + (y - 1)) * 32;
#pragma unroll
        for (int i = 0; i < 8; i++) {
            float4 v = reinterpret_cast<const float4*>(src)[i];
            s_t[c][i * 4 + 0] = v.x; s_t[c][i * 4 + 1] = v.y;
            s_t[c][i * 4 + 2] = v.z; s_t[c][i * 4 + 3] = v.w;
        }
    }
    __syncthreads();
    for (int xx = 0; xx < 34; xx++) {
        float v = (rowvalid && xx >= 1 && xx <= 32) ? s_t[c][xx - 1] : 0.f;
        __nv_bfloat16 hi = __float2bfloat16(v);
        __nv_bfloat16 lo = __float2bfloat16(v - __bfloat162float(hi));
        int base = (((b * 2) * 34 + y) * 34 + xx) * 256 + c;
        g_xbfT[base]              = hi;
        g_xbfT[base + 34*34*256]  = lo;
    }
}

// ---------------- 1c) wo transpose ----------------
__global__ void transpose_wo_kernel(const float* __restrict__ wo) {
    __shared__ float tile[32][33];
    const int c0 = blockIdx.x * 32, o0 = blockIdx.y * 32;
#pragma unroll
    for (int i = 0; i < 4; i++)
        tile[threadIdx.y + i * 8][threadIdx.x] = wo[(o0 + threadIdx.y + i * 8) * 256 + c0 + threadIdx.x];
    __syncthreads();
#pragma unroll
    for (int i = 0; i < 4; i++)
        g_woT[(c0 + threadIdx.y + i * 8) * 256 + o0 + threadIdx.x] =
            tile[threadIdx.x][threadIdx.y + i * 8];
}

// ---------------- 2) conv via mma.sync (R11 version) ----------------
__global__ void __launch_bounds__(256) conv_mma_kernel() {
    const int nt  = blockIdx.x;
    const int p   = blockIdx.y;
    const int b   = blockIdx.z;
    const int tid = threadIdx.x, warp = tid >> 5, lane = tid & 31;
    const int wm = warp & 1, wn = warp >> 1;
    const int g = lane >> 2, t = lane & 3;
    const int px_warp = nt * 64 + wm * 32;

    float acc[2][8][4];
#pragma unroll
    for (int mt = 0; mt < 2; mt++)
#pragma unroll
        for (int n8 = 0; n8 < 8; n8++)
#pragma unroll
            for (int r = 0; r < 4; r++) acc[mt][n8][r] = 0.f;

    const ulonglong2* wfrag16 = reinterpret_cast<const ulonglong2*>(g_wfragB);

    for (int tap = 0; tap < 9; tap++) {
        const int ky = tap / 3, kx = tap - ky * 3;
        for (int kc = 0; kc < 16; kc++) {
            uint32_t afr[2][2][4];
#pragma unroll
            for (int mt = 0; mt < 2; mt++) {
                const int px  = px_warp + mt * 16 + g;
                const int y   = (px >> 5) + ky;
                const int x   = (px & 31) + kx;
                const int ic0 = kc * 16 + t * 4;
#pragma unroll
                for (int sp = 0; sp < 2; sp++) {
                    const __nv_bfloat16* xp =
                        g_xbfT + (((b * 2 + sp) * 34 + y) * 34 + x) * 256 + ic0;
                    ull v0 = *reinterpret_cast<const ull*>(xp);
                    ull v1 = *reinterpret_cast<const ull*>(xp + 2048);
                    afr[sp][mt][0] = (uint32_t)v0;
                    afr[sp][mt][2] = (uint32_t)(v0 >> 32);
                    afr[sp][mt][1] = (uint32_t)v1;
                    afr[sp][mt][3] = (uint32_t)(v1 >> 32);
                }
            }
            uint32_t bfr[2][8][2];
#pragma unroll
            for (int sp = 0; sp < 2; sp++) {
                const ulonglong2* wb = wfrag16 +
                    ((((p * 9 + tap) * 2 + sp) * 16 + kc) * 16) * 32 + lane;
#pragma unroll
                for (int n4 = 0; n4 < 4; n4++) {
                    ulonglong2 v = wb[(wn * 4 + n4) * 32];
                    bfr[sp][2 * n4][0]     = (uint32_t)v.x;
                    bfr[sp][2 * n4][1]     = (uint32_t)(v.x >> 32);
                    bfr[sp][2 * n4 + 1][0] = (uint32_t)v.y;
                    bfr[sp][2 * n4 + 1][1] = (uint32_t)(v.y >> 32);
                }
            }
#pragma unroll
            for (int combo = 0; combo < 3; combo++) {
                const int ws = combo >> 1, xs = combo & 1;
#pragma unroll
                for (int mt = 0; mt < 2; mt++)
#pragma unroll
                    for (int n8 = 0; n8 < 8; n8++)
                        mma16816(acc[mt][n8], afr[xs][mt], bfr[ws][n8]);
            }
        }
    }

    float s = 0.f, sq = 0.f;
#pragma unroll
    for (int mt = 0; mt < 2; mt++)
#pragma unroll
        for (int n8 = 0; n8 < 8; n8++)
#pragma unroll
            for (int r = 0; r < 4; r++) {
                float v  = acc[mt][n8][r];
                int   px = px_warp + mt * 16 + g + ((r >> 1) << 3);
                int   oc = wn * 64 + n8 * 8 + t * 2 + (r & 1);
                g_act[p][(b * 256 + oc) * 1024 + px] = v;
                s += v; sq += v * v;
            }
    __shared__ float red[512];
    red[tid] = s; red[tid + 256] = sq;
    __syncthreads();
    for (int st = 128; st > 0; st >>= 1) {
        if (tid < st) { red[tid] += red[tid + st]; red[tid + 256] += red[tid + 256 + st]; }
        __syncthreads();
    }
    if (tid == 0) {
        g_part[p][b][nt][0] = red[0];
        g_part[p][b][nt][1] = red[256];
    }
}

// ---------------- 3) GroupNorm(1) + exact GELU ----------------
__global__ void gn_gelu_kernel(const float* __restrict__ gq, const float* __restrict__ bq,
                               const float* __restrict__ gk, const float* __restrict__ bk,
                               const float* __restrict__ gv, const float* __restrict__ bv) {
    const int chunk = blockIdx.x;
    const int b     = blockIdx.y;
    const int p     = blockIdx.z;
    const float* gg = (p == 0) ? gq : (p == 1) ? gk : gv;
    const float* bb = (p == 0) ? bq : (p == 1) ? bk : bv;

    __shared__ float s_mu, s_rs;
    if (threadIdx.x < 16) {
        float s  = g_part[p][b][threadIdx.x][0];
        float sq = g_part[p][b][threadIdx.x][1];
#pragma unroll
        for (int o = 8; o > 0; o >>= 1) {
            s  += __shfl_down_sync(0x0000ffffu, s,  o);
            sq += __shfl_down_sync(0x0000ffffu, sq, o);
        }
        if (threadIdx.x == 0) {
            float mu  = s / (float)NPER;
            float var = sq / (float)NPER - mu * mu;
            s_mu = mu;
            s_rs = rsqrtf(var + 1e-6f);
        }
    }
    __syncthreads();
    const float mu = s_mu, rs = s_rs;

    float* base = &g_act[p][b * NPER + chunk * 32768];
    for (int i = threadIdx.x; i < 8192; i += 256) {
        float4 v = reinterpret_cast<float4*>(base)[i];
        int c = (chunk * 32768 + i * 4) >> 10;
        float gc = gg[c], bc = bb[c];
        float t0 = (v.x - mu) * rs * gc + bc;
        float t1 = (v.y - mu) * rs * gc + bc;
        float t2 = (v.z - mu) * rs * gc + bc;
        float t3 = (v.w - mu) * rs * gc + bc;
        v.x = 0.5f * t0 * (1.0f + erff(t0 * 0.70710678118654752f));
        v.y = 0.5f * t1 * (1.0f + erff(t1 * 0.70710678118654752f));
        v.z = 0.5f * t2 * (1.0f + erff(t2 * 0.70710678118654752f));
        v.w = 0.5f * t3 * (1.0f + erff(t3 * 0.70710678118654752f));
        reinterpret_cast<float4*>(base)[i] = v;
    }
}

// ---------------- 4) tensor-core flash attention ----------------
// grid (8 qtiles of 128, 8 h, 8 b), block 128 (4 warps x 32 q rows), kv-tile 32
__global__ void __launch_bounds__(128) attn_kernel(const float* __restrict__ bias_table) {
    const int qt = blockIdx.x, h = blockIdx.y, b = blockIdx.z;
    const int tid = threadIdx.x, warp = tid >> 5, lane = tid & 31;
    const int g = lane >> 2, t = lane & 3;
    const int qw0 = qt * 128 + warp * 32;

    __shared__ float    s_bias[BIASN + 3];
    __shared__ uint32_t sK[2][32][17];   // [split][kv][dpair]
    __shared__ uint32_t sV[2][32][17];   // [split][d][kvpair]

    for (int i = tid; i < BIASN; i += 128)
        s_bias[i] = bias_table[i * HEADS + h];

    const float* aq = &g_act[0][(b * 256 + h * DHEAD) * NTOK];
    const float* ak = &g_act[1][(b * 256 + h * DHEAD) * NTOK];
    const float* av = &g_act[2][(b * 256 + h * DHEAD) * NTOK];

    // Q fragments once: qf[split][mt][kc][4]
    uint32_t qf[2][2][2][4];
#pragma unroll
    for (int mt = 0; mt < 2; mt++) {
        const int row0 = qw0 + mt * 16 + g;
#pragma unroll
        for (int kc = 0; kc < 2; kc++) {
            const int kd = kc * 16;
            float a00 = aq[(kd + 2 * t    ) * NTOK + row0];
            float a01 = aq[(kd + 2 * t + 1) * NTOK + row0];
            float a10 = aq[(kd + 2 * t    ) * NTOK + row0 + 8];
            float a11 = aq[(kd + 2 * t + 1) * NTOK + row0 + 8];
            float a20 = aq[(kd + 8 + 2 * t    ) * NTOK + row0];
            float a21 = aq[(kd + 8 + 2 * t + 1) * NTOK + row0];
            float a30 = aq[(kd + 8 + 2 * t    ) * NTOK + row0 + 8];
            float a31 = aq[(kd + 8 + 2 * t + 1) * NTOK + row0 + 8];
            split2(a00, a01, qf[0][mt][kc][0], qf[1][mt][kc][0]);
            split2(a10, a11, qf[0][mt][kc][1], qf[1][mt][kc][1]);
            split2(a20, a21, qf[0][mt][kc][2], qf[1][mt][kc][2]);
            split2(a30, a31, qf[0][mt][kc][3], qf[1][mt][kc][3]);
        }
    }

    // per-row coords (for bias index)
    int yq[2][2], xq[2][2];
#pragma unroll
    for (int mt = 0; mt < 2; mt++)
#pragma unroll
        for (int rh = 0; rh < 2; rh++) {
            int q = qw0 + mt * 16 + g + rh * 8;
            yq[mt][rh] = q >> 5; xq[mt][rh] = q & 31;
        }

    float m[2][2], l[2][2];
    float o[2][4][4];
#pragma unroll
    for (int mt = 0; mt < 2; mt++)
#pragma unroll
        for (int rh = 0; rh < 2; rh++) { m[mt][rh] = -1e30f; l[mt][rh] = 0.f; }
#pragma unroll
    for (int mt = 0; mt < 2; mt++)
#pragma unroll
        for (int n = 0; n < 4; n++)
#pragma unroll
            for (int r = 0; r < 4; r++) o[mt][n][r] = 0.f;

    for (int kt = 0; kt < 32; kt++) {
        const int kv0 = kt * 32;
        __syncthreads();
        // fill K: [kv][dpair] packed hi/lo
        for (int e = tid; e < 512; e += 128) {
            int kv = e & 31, dp = e >> 5;
            float f0 = ak[(2 * dp)     * NTOK + kv0 + kv];
            float f1 = ak[(2 * dp + 1) * NTOK + kv0 + kv];
            uint32_t hi, lo;
            split2(f0, f1, hi, lo);
            sK[0][kv][dp] = hi; sK[1][kv][dp] = lo;
        }
        // fill V: [d][kvpair]
        for (int e = tid; e < 512; e += 128) {
            int kvp = e & 15, d = e >> 4;
            float2 vv = *reinterpret_cast<const float2*>(&av[d * NTOK + kv0 + 2 * kvp]);
            uint32_t hi, lo;
            split2(vv.x, vv.y, hi, lo);
            sV[0][d][kvp] = hi; sV[1][d][kvp] = lo;
        }
        __syncthreads();

        // ---- QK ----
        float sc[2][4][4];
#pragma unroll
        for (int mt = 0; mt < 2; mt++)
#pragma unroll
            for (int j = 0; j < 4; j++)
#pragma unroll
                for (int r = 0; r < 4; r++) sc[mt][j][r] = 0.f;

#pragma unroll
        for (int kc = 0; kc < 2; kc++) {
            uint32_t kf[2][4][2];
#pragma unroll
            for (int sp = 0; sp < 2; sp++)
#pragma unroll
                for (int j = 0; j < 4; j++) {
                    kf[sp][j][0] = sK[sp][j * 8 + g][kc * 8 + t];
                    kf[sp][j][1] = sK[sp][j * 8 + g][kc * 8 + 4 + t];
                }
#pragma unroll
            for (int mt = 0; mt < 2; mt++)
#pragma unroll
                for (int j = 0; j < 4; j++) {
                    mma16816(sc[mt][j], qf[0][mt][kc], kf[0][j]);
                    mma16816(sc[mt][j], qf[1][mt][kc], kf[0][j]);
                    mma16816(sc[mt][j], qf[0][mt][kc], kf[1][j]);
                }
        }

        // ---- bias add ----
#pragma unroll
        for (int mt = 0; mt < 2; mt++)
#pragma unroll
            for (int j = 0; j < 4; j++)
#pragma unroll
                for (int r = 0; r < 4; r++) {
                    int kv = kv0 + j * 8 + 2 * t + (r & 1);
                    int rh = r >> 1;
                    int idx = (yq[mt][rh] - (kv >> 5) + 31) * 63 + (xq[mt][rh] - (kv & 31) + 31);
                    sc[mt][j][r] += s_bias[idx];
                }

        // ---- online softmax ----
#pragma unroll
        for (int mt = 0; mt < 2; mt++)
#pragma unroll
            for (int rh = 0; rh < 2; rh++) {
                float tm = sc[mt][0][2 * rh];
#pragma unroll
                for (int j = 0; j < 4; j++) {
                    tm = fmaxf(tm, sc[mt][j][2 * rh]);
                    tm = fmaxf(tm, sc[mt][j][2 * rh + 1]);
                }
                tm = fmaxf(tm, __shfl_xor_sync(0xffffffffu, tm, 1));
                tm = fmaxf(tm, __shfl_xor_sync(0xffffffffu, tm, 2));
                float mo = m[mt][rh];
                float mn = fmaxf(mo, tm);
                float scale = __expf(mo - mn);
                m[mt][rh] = mn;
                l[mt][rh] *= scale;
#pragma unroll
                for (int n = 0; n < 4; n++) {
                    o[mt][n][2 * rh]     *= scale;
                    o[mt][n][2 * rh + 1] *= scale;
                }
            }
#pragma unroll
        for (int mt = 0; mt < 2; mt++)
#pragma unroll
            for (int j = 0; j < 4; j++)
#pragma unroll
                for (int r = 0; r < 4; r++) {
                    float p = __expf(sc[mt][j][r] - m[mt][r >> 1]);
                    sc[mt][j][r] = p;
                    l[mt][r >> 1] += p;
                }

        // ---- PV ----
#pragma unroll
        for (int kk = 0; kk < 2; kk++) {
            uint32_t vf[2][4][2];
#pragma unroll
            for (int sp = 0; sp < 2; sp++)
#pragma unroll
                for (int n = 0; n < 4; n++) {
                    vf[sp][n][0] = sV[sp][n * 8 + g][kk * 8 + t];
                    vf[sp][n][1] = sV[sp][n * 8 + g][kk * 8 + 4 + t];
                }
#pragma unroll
            for (int mt = 0; mt < 2; mt++) {
                uint32_t pf[2][4];
                split2(sc[mt][2 * kk][0],     sc[mt][2 * kk][1],     pf[0][0], pf[1][0]);
                split2(sc[mt][2 * kk][2],     sc[mt][2 * kk][3],     pf[0][1], pf[1][1]);
                split2(sc[mt][2 * kk + 1][0], sc[mt][2 * kk + 1][1], pf[0][2], pf[1][2]);
                split2(sc[mt][2 * kk + 1][2], sc[mt][2 * kk + 1][3], pf[0][3], pf[1][3]);
#pragma unroll
                for (int n = 0; n < 4; n++) {
                    mma16816(o[mt][n], pf[0], vf[0][n]);
                    mma16816(o[mt][n], pf[1], vf[0][n]);
                    mma16816(o[mt][n], pf[0], vf[1][n]);
                }
            }
        }
    }

    // final: l reduce across quad, normalize, write
    float linv[2][2];
#pragma unroll
    for (int mt = 0; mt < 2; mt++)
#pragma unroll
        for (int rh = 0; rh < 2; rh++) {
            float ls = l[mt][rh];
            ls += __shfl_xor_sync(0xffffffffu, ls, 1);
            ls += __shfl_xor_sync(0xffffffffu, ls, 2);
            linv[mt][rh] = 1.f / ls;
        }
    float* ao = &g_attn[(b * 256 + h * DHEAD) * NTOK];
#pragma unroll
    for (int mt = 0; mt < 2; mt++)
#pragma unroll
        for (int n = 0; n < 4; n++)
#pragma unroll
            for (int r = 0; r < 4; r++) {
                int q = qw0 + mt * 16 + g + (r >> 1) * 8;
                int d = n * 8 + 2 * t + (r & 1);
                ao[d * NTOK + q] = o[mt][n][r] * linv[mt][r >> 1];
            }
}

// ---------------- 5) 1x1 output projection ----------------
__global__ void outproj_kernel(const float* __restrict__ bo, float* __restrict__ out) {
    const int nt = blockIdx.x;
    const int b  = blockIdx.y;
    const int oc = threadIdx.x;

    __shared__ __align__(16) float s_a[256 * 32];
    for (int e = oc; e < 8192; e += 256) {
        int c = e >> 5, px = e & 31;
        s_a[e] = g_attn[(b * 256 + c) * NTOK + nt * 32 + px];
    }
    __syncthreads();

    ull acc[16];
#pragma unroll
    for (int p = 0; p < 16; p++) acc[p] = 0ull;

    for (int c = 0; c < 256; c++) {
        float wv = g_woT[c * 256 + oc];
        ull w2 = pack2(wv, wv);
        const ulonglong2* arow2 = reinterpret_cast<const ulonglong2*>(&s_a[c * 32]);
#pragma unroll
        for (int p8 = 0; p8 < 8; p8++) {
            ulonglong2 vv = arow2[p8];
            ffma2(acc[2 * p8],     w2, vv.x);
            ffma2(acc[2 * p8 + 1], w2, vv.y);
        }
    }

    const float bb = bo[oc];
    float* op = out + (b * 256 + oc) * NTOK + nt * 32;
#pragma unroll
    for (int p = 0; p < 16; p += 2) {
        float4 v4 = make_float4(lo2(acc[p]) + bb,     hi2(acc[p]) + bb,
                                lo2(acc[p + 1]) + bb, hi2(acc[p + 1]) + bb);
        *reinterpret_cast<float4*>(op + 2 * p) = v4;
    }
}

// ---------------- launch ----------------
extern "C" void kernel_launch(void* const* d_in, const int* in_sizes, int n_in,
                              void* d_out, int out_size) {
    const float* x  = (const float*)d_in[0];
    const float* wq = (const float*)d_in[1];
    const float* wk = (const float*)d_in[2];
    const float* wv = (const float*)d_in[3];
    const float* gq = (const float*)d_in[4];
    const float* bq = (const float*)d_in[5];
    const float* gk = (const float*)d_in[6];
    const float* bk = (const float*)d_in[7];
    const float* gv = (const float*)d_in[8];
    const float* bv = (const float*)d_in[9];
    const float* bt = (const float*)d_in[10];
    const float* wo = (const float*)d_in[11];
    const float* bo = (const float*)d_in[12];
    float* out = (float*)d_out;

    prep_w_kernel<<<dim3(64, 9, 3), 256>>>(wq, wk, wv);
    prep_x_kernel<<<dim3(34, BATCH), 256>>>(x);
    transpose_wo_kernel<<<dim3(8, 8), dim3(32, 8)>>>(wo);
    conv_mma_kernel<<<dim3(16, 3, BATCH), 256>>>();
    gn_gelu_kernel<<<dim3(8, BATCH, 3), 256>>>(gq, bq, gk, bk, gv, bv);
    attn_kernel<<<dim3(8, HEADS, BATCH), 128>>>(bt);
    outproj_kernel<<<dim3(32, BATCH), 256>>>(bo, out);
}